// round 11
// baseline (speedup 1.0000x reference)
#include <cuda_runtime.h>
#include <cstdint>

// ----------------------------------------------------------------------------
// MultiHeadAttention, fp32 semantics.
// Stage 1/3: 3xTF32 mma.sync GEMM (split fp32 = hi+lo, 3 MMAs) — tensor pipe.
// Stage 2: flash attention Br=Bc=64 (R8-validated, unchanged).
// ----------------------------------------------------------------------------

constexpr int BATCH = 2;
constexpr int SEQ   = 2048;
constexpr int DM    = 768;
constexpr int NH    = 12;
constexpr int HD    = 64;
constexpr int BH    = BATCH * NH;   // 24
constexpr int MTOT  = BATCH * SEQ;  // 4096
constexpr int NTILES = SEQ / 64;    // 32
constexpr float NEGV  = -10000.0f;
constexpr float SCALE = 0.125f;

constexpr int BK = 32;              // k-chunk
constexpr int STR = 66;             // smem floats per row: 32*2 + 2 pad
// dynamic smem: As[128*66] + Bs[128*66] floats = 67584 bytes
constexpr int GEMM_SMEM = 2 * 128 * STR * (int)sizeof(float);

__device__ float g_Q[BATCH * NH * SEQ * HD];
__device__ float g_K[BATCH * NH * SEQ * HD];
__device__ float g_V[BATCH * NH * SEQ * HD];
__device__ float g_O[BATCH * NH * SEQ * HD];

__device__ __forceinline__ float f4_get(const float4& v, int j) {
    return j == 0 ? v.x : j == 1 ? v.y : j == 2 ? v.z : v.w;
}
__device__ __forceinline__ uint32_t tf32_bits(float x) {
    uint32_t u;
    asm("cvt.rna.tf32.f32 %0, %1;" : "=r"(u) : "f"(x));
    return u;
}
// write hi/lo tf32 pair for value x at interleaved smem slot
__device__ __forceinline__ void put_hilo(float* dst, float x) {
    uint32_t hb = tf32_bits(x);
    float hf = __uint_as_float(hb);
    uint32_t lb = tf32_bits(x - hf);
    dst[0] = __uint_as_float(hb);
    dst[1] = __uint_as_float(lb);
}
__device__ __forceinline__ void mma_tf32(float d[4], const uint32_t a[4], const uint32_t b[2]) {
    asm volatile(
        "mma.sync.aligned.m16n8k8.row.col.f32.tf32.tf32.f32 "
        "{%0,%1,%2,%3}, {%4,%5,%6,%7}, {%8,%9}, {%0,%1,%2,%3};"
        : "+f"(d[0]), "+f"(d[1]), "+f"(d[2]), "+f"(d[3])
        : "r"(a[0]), "r"(a[1]), "r"(a[2]), "r"(a[3]), "r"(b[0]), "r"(b[1]));
}

// ----------------------------------------------------------------------------
// Core 3xTF32 mainloop: block 128(M)x128(N), 8 warps -> warp tile 64x32.
// As/Bs: interleaved hi/lo, As[(m*66)+(k*2)+sel], Bs[(n*66)+(k*2)+sel].
// acc[am][bn][4] accumulated over all 24 k-chunks.  Caller fills smem per
// chunk via the lambda-free fill sections below (kernels differ only in A fill
// and epilogue).
// ----------------------------------------------------------------------------
struct FragState {
    float acc[4][4][4];
};

__device__ __forceinline__ void gemm_chunk_compute(
    const float* As, const float* Bs, float acc[4][4][4], int lane, int wm, int wn)
{
    const int r = lane >> 2;       // 0..7
    const int c = lane & 3;        // 0..3
    #pragma unroll
    for (int kk8 = 0; kk8 < 4; ++kk8) {
        const int kA = kk8 * 8 + c;
        // B fragments for this warp's 4 n-atoms
        uint32_t bh[4][2], bl[4][2];
        #pragma unroll
        for (int bn = 0; bn < 4; ++bn) {
            int n = wn * 32 + bn * 8 + r;
            float2 p0 = *reinterpret_cast<const float2*>(&Bs[n * STR + kA * 2]);
            float2 p1 = *reinterpret_cast<const float2*>(&Bs[n * STR + (kA + 4) * 2]);
            bh[bn][0] = __float_as_uint(p0.x); bl[bn][0] = __float_as_uint(p0.y);
            bh[bn][1] = __float_as_uint(p1.x); bl[bn][1] = __float_as_uint(p1.y);
        }
        #pragma unroll
        for (int am = 0; am < 4; ++am) {
            int m = wm * 64 + am * 16 + r;
            float2 q0 = *reinterpret_cast<const float2*>(&As[m * STR + kA * 2]);
            float2 q1 = *reinterpret_cast<const float2*>(&As[(m + 8) * STR + kA * 2]);
            float2 q2 = *reinterpret_cast<const float2*>(&As[m * STR + (kA + 4) * 2]);
            float2 q3 = *reinterpret_cast<const float2*>(&As[(m + 8) * STR + (kA + 4) * 2]);
            uint32_t ah[4] = {__float_as_uint(q0.x), __float_as_uint(q1.x),
                              __float_as_uint(q2.x), __float_as_uint(q3.x)};
            uint32_t al[4] = {__float_as_uint(q0.y), __float_as_uint(q1.y),
                              __float_as_uint(q2.y), __float_as_uint(q3.y)};
            #pragma unroll
            for (int bn = 0; bn < 4; ++bn) {
                mma_tf32(acc[am][bn], ah, bh[bn]);
                mma_tf32(acc[am][bn], ah, bl[bn]);
                mma_tf32(acc[am][bn], al, bh[bn]);
            }
        }
    }
}

// ----------------------------------------------------------------------------
// Stage 1: QKV projections.  grid = (DM/128, MTOT/128, 3), 256 threads.
// ----------------------------------------------------------------------------
__global__ void __launch_bounds__(256) qkv_proj_kernel(
    const float* __restrict__ q, const float* __restrict__ k, const float* __restrict__ v,
    const float* __restrict__ Wq, const float* __restrict__ Wk, const float* __restrict__ Wv)
{
    extern __shared__ float smem[];
    float* As = smem;
    float* Bs = smem + 128 * STR;

    const int z = blockIdx.z;
    const float* X = (z == 0) ? q : (z == 1) ? k : v;
    const float* W = (z == 0) ? Wq : (z == 1) ? Wk : Wv;
    float* out = (z == 0) ? g_Q : (z == 1) ? g_K : g_V;

    const int n0 = blockIdx.x * 128;
    const int m0 = blockIdx.y * 128;
    const int tid = threadIdx.x;
    const int lane = tid & 31;
    const int wid = tid >> 5;
    const int wm = wid >> 2, wn = wid & 3;

    const int fm = tid >> 1;              // A fill row
    const int fkb = (tid & 1) * 16;       // A fill k-base
    const int fn = tid & 127;             // B fill col
    const int fkb2 = (tid >> 7) * 16;     // B fill k-base

    float acc[4][4][4] = {};

    for (int k0 = 0; k0 < DM; k0 += BK) {
        // fill A: 16 consecutive k of row fm
        {
            const float* src = &X[(size_t)(m0 + fm) * DM + k0 + fkb];
            #pragma unroll
            for (int j4 = 0; j4 < 4; ++j4) {
                float4 f = *reinterpret_cast<const float4*>(src + j4 * 4);
                put_hilo(&As[fm * STR + (fkb + j4 * 4 + 0) * 2], f.x);
                put_hilo(&As[fm * STR + (fkb + j4 * 4 + 1) * 2], f.y);
                put_hilo(&As[fm * STR + (fkb + j4 * 4 + 2) * 2], f.z);
                put_hilo(&As[fm * STR + (fkb + j4 * 4 + 3) * 2], f.w);
            }
        }
        // fill B: Bs[n][k] = W[k0+k][n0+n], coalesced over n
        {
            #pragma unroll 4
            for (int j = 0; j < 16; ++j) {
                float w = W[(size_t)(k0 + fkb2 + j) * DM + n0 + fn];
                put_hilo(&Bs[fn * STR + (fkb2 + j) * 2], w);
            }
        }
        __syncthreads();
        gemm_chunk_compute(As, Bs, acc, lane, wm, wn);
        __syncthreads();
    }

    // epilogue -> head-major [B,H,S,64]
    const int r = lane >> 2;
    const int c2 = (lane & 3) * 2;
    #pragma unroll
    for (int am = 0; am < 4; ++am) {
        #pragma unroll
        for (int bn = 0; bn < 4; ++bn) {
            int col = n0 + wn * 32 + bn * 8 + c2;
            int head = col >> 6, d0 = col & 63;
            int mA = m0 + wm * 64 + am * 16 + r;
            int bb = mA >> 11, ss = mA & (SEQ - 1);
            *reinterpret_cast<float2*>(&out[(((size_t)(bb * NH + head)) * SEQ + ss) * HD + d0]) =
                make_float2(acc[am][bn][0], acc[am][bn][1]);
            int mB = mA + 8;
            int bb2 = mB >> 11, ss2 = mB & (SEQ - 1);
            *reinterpret_cast<float2*>(&out[(((size_t)(bb2 * NH + head)) * SEQ + ss2) * HD + d0]) =
                make_float2(acc[am][bn][2], acc[am][bn][3]);
        }
    }
}

// ----------------------------------------------------------------------------
// Stage 3: output projection.  grid = (DM/128, MTOT/128), 256 threads.
// A gathered from head-major g_O.
// ----------------------------------------------------------------------------
__global__ void __launch_bounds__(256) out_proj_kernel(
    const float* __restrict__ Wo, float* __restrict__ out)
{
    extern __shared__ float smem[];
    float* As = smem;
    float* Bs = smem + 128 * STR;

    const int n0 = blockIdx.x * 128;
    const int m0 = blockIdx.y * 128;
    const int tid = threadIdx.x;
    const int lane = tid & 31;
    const int wid = tid >> 5;
    const int wm = wid >> 2, wn = wid & 3;

    const int fm = tid >> 1;
    const int fkb = (tid & 1) * 16;
    const int fn = tid & 127;
    const int fkb2 = (tid >> 7) * 16;

    const int gm = m0 + fm;
    const int gbb = gm >> 11;
    const int gss = gm & (SEQ - 1);

    float acc[4][4][4] = {};

    for (int k0 = 0; k0 < DM; k0 += BK) {
        // fill A: kidx=k0+fkb is a multiple of 16 -> 16 consecutive k in one head
        {
            int kidx = k0 + fkb;
            int h = kidx >> 6, dd = kidx & 63;
            const float* src = &g_O[(((size_t)(gbb * NH + h)) * SEQ + gss) * HD + dd];
            #pragma unroll
            for (int j4 = 0; j4 < 4; ++j4) {
                float4 f = *reinterpret_cast<const float4*>(src + j4 * 4);
                put_hilo(&As[fm * STR + (fkb + j4 * 4 + 0) * 2], f.x);
                put_hilo(&As[fm * STR + (fkb + j4 * 4 + 1) * 2], f.y);
                put_hilo(&As[fm * STR + (fkb + j4 * 4 + 2) * 2], f.z);
                put_hilo(&As[fm * STR + (fkb + j4 * 4 + 3) * 2], f.w);
            }
        }
        {
            #pragma unroll 4
            for (int j = 0; j < 16; ++j) {
                float w = Wo[(size_t)(k0 + fkb2 + j) * DM + n0 + fn];
                put_hilo(&Bs[fn * STR + (fkb2 + j) * 2], w);
            }
        }
        __syncthreads();
        gemm_chunk_compute(As, Bs, acc, lane, wm, wn);
        __syncthreads();
    }

    const int r = lane >> 2;
    const int c2 = (lane & 3) * 2;
    #pragma unroll
    for (int am = 0; am < 4; ++am) {
        #pragma unroll
        for (int bn = 0; bn < 4; ++bn) {
            int col = n0 + wn * 32 + bn * 8 + c2;
            int mA = m0 + wm * 64 + am * 16 + r;
            *reinterpret_cast<float2*>(&out[(size_t)mA * DM + col]) =
                make_float2(acc[am][bn][0], acc[am][bn][1]);
            *reinterpret_cast<float2*>(&out[(size_t)(mA + 8) * DM + col]) =
                make_float2(acc[am][bn][2], acc[am][bn][3]);
        }
    }
}

// ----------------------------------------------------------------------------
// Stage 2: flash attention (R8-validated, unchanged).
// ----------------------------------------------------------------------------
__global__ void __launch_bounds__(256) flash_kernel(
    const int* __restrict__ attn_mask, const int* __restrict__ mask_future)
{
    extern __shared__ float sm[];
    float* Qt = sm;
    float* Kt = sm + 4096;
    float* Vs = sm + 8192;
    float* Ps = Kt;

    const int tid = threadIdx.x;
    const int tx = tid & 15, ty = tid >> 4;
    const int rr = ty * 4, cc = tx * 4;
    const int qt = (int)gridDim.x - 1 - (int)blockIdx.x;
    const int bh = blockIdx.y;
    const int b  = bh / NH;
    const int q0 = qt * 64;
    const bool causal = (mask_future[0] != 0);

    {
        int j = tid & 63;
        int dq = (tid >> 6) * 16;
        #pragma unroll
        for (int qd = 0; qd < 4; ++qd) {
            int d = dq + qd * 4;
            float4 qv = *reinterpret_cast<const float4*>(
                &g_Q[(((size_t)bh) * SEQ + q0 + j) * HD + d]);
            Qt[(d + 0) * 64 + j] = qv.x;
            Qt[(d + 1) * 64 + j] = qv.y;
            Qt[(d + 2) * 64 + j] = qv.z;
            Qt[(d + 3) * 64 + j] = qv.w;
        }
    }

    float m_i[4], l_i[4], o[4][4];
    #pragma unroll
    for (int i = 0; i < 4; ++i) {
        m_i[i] = -1e30f;
        l_i[i] = 0.0f;
        o[i][0] = o[i][1] = o[i][2] = o[i][3] = 0.0f;
    }

    int limit = causal ? (qt + 1) : NTILES;

    for (int kt = 0; kt < NTILES; ++kt) {
        if (kt >= limit) break;
        const int k0 = kt * 64;
        __syncthreads();

        {
            int j = tid & 63;
            int dq = (tid >> 6) * 16;
            #pragma unroll
            for (int qd = 0; qd < 4; ++qd) {
                int d = dq + qd * 4;
                float4 kv = *reinterpret_cast<const float4*>(
                    &g_K[(((size_t)bh) * SEQ + k0 + j) * HD + d]);
                Kt[(d + 0) * 64 + j] = kv.x;
                Kt[(d + 1) * 64 + j] = kv.y;
                Kt[(d + 2) * 64 + j] = kv.z;
                Kt[(d + 3) * 64 + j] = kv.w;
            }
        }
        #pragma unroll
        for (int qd = 0; qd < 4; ++qd) {
            int fi = tid + qd * 256;
            int row = fi >> 4;
            int col = (fi & 15) * 4;
            *reinterpret_cast<float4*>(&Vs[row * 64 + col]) =
                *reinterpret_cast<const float4*>(&g_V[(((size_t)bh) * SEQ + k0 + row) * HD + col]);
        }
        int mk[4];
        #pragma unroll
        for (int j = 0; j < 4; ++j)
            mk[j] = attn_mask[b * SEQ + k0 + cc + j];
        __syncthreads();

        float sacc[4][4] = {};
        #pragma unroll 16
        for (int d = 0; d < 64; ++d) {
            float4 qa = *reinterpret_cast<float4*>(&Qt[d * 64 + rr]);
            float4 kb = *reinterpret_cast<float4*>(&Kt[d * 64 + cc]);
            sacc[0][0] += qa.x * kb.x; sacc[0][1] += qa.x * kb.y; sacc[0][2] += qa.x * kb.z; sacc[0][3] += qa.x * kb.w;
            sacc[1][0] += qa.y * kb.x; sacc[1][1] += qa.y * kb.y; sacc[1][2] += qa.y * kb.z; sacc[1][3] += qa.y * kb.w;
            sacc[2][0] += qa.z * kb.x; sacc[2][1] += qa.z * kb.y; sacc[2][2] += qa.z * kb.z; sacc[2][3] += qa.z * kb.w;
            sacc[3][0] += qa.w * kb.x; sacc[3][1] += qa.w * kb.y; sacc[3][2] += qa.w * kb.z; sacc[3][3] += qa.w * kb.w;
        }
        __syncthreads();

        #pragma unroll
        for (int i = 0; i < 4; ++i) {
            int ig = q0 + rr + i;
            #pragma unroll
            for (int j = 0; j < 4; ++j) {
                int jg = k0 + cc + j;
                float sv = sacc[i][j] * SCALE;
                if (causal && jg > ig) sv += NEGV;
                if (mk[j] == 0) sv = NEGV;
                sacc[i][j] = sv;
            }
        }

        #pragma unroll
        for (int i = 0; i < 4; ++i) {
            float tm = fmaxf(fmaxf(sacc[i][0], sacc[i][1]), fmaxf(sacc[i][2], sacc[i][3]));
            #pragma unroll
            for (int off = 8; off; off >>= 1)
                tm = fmaxf(tm, __shfl_xor_sync(0xffffffffu, tm, off));
            float mnew = fmaxf(m_i[i], tm);
            float alpha = __expf(m_i[i] - mnew);
            float ps = 0.0f;
            #pragma unroll
            for (int j = 0; j < 4; ++j) {
                float p = __expf(sacc[i][j] - mnew);
                sacc[i][j] = p;
                ps += p;
            }
            #pragma unroll
            for (int off = 8; off; off >>= 1)
                ps += __shfl_xor_sync(0xffffffffu, ps, off);
            l_i[i] = l_i[i] * alpha + ps;
            m_i[i] = mnew;
            o[i][0] *= alpha; o[i][1] *= alpha; o[i][2] *= alpha; o[i][3] *= alpha;
        }

        #pragma unroll
        for (int i = 0; i < 4; ++i)
            *reinterpret_cast<float4*>(&Ps[(rr + i) * 64 + cc]) =
                make_float4(sacc[i][0], sacc[i][1], sacc[i][2], sacc[i][3]);
        __syncthreads();

        #pragma unroll 8
        for (int j4 = 0; j4 < 64; j4 += 4) {
            float4 p0 = *reinterpret_cast<float4*>(&Ps[(rr + 0) * 64 + j4]);
            float4 p1 = *reinterpret_cast<float4*>(&Ps[(rr + 1) * 64 + j4]);
            float4 p2 = *reinterpret_cast<float4*>(&Ps[(rr + 2) * 64 + j4]);
            float4 p3 = *reinterpret_cast<float4*>(&Ps[(rr + 3) * 64 + j4]);
            #pragma unroll
            for (int jj = 0; jj < 4; ++jj) {
                float4 vv = *reinterpret_cast<float4*>(&Vs[(j4 + jj) * 64 + cc]);
                float a0 = f4_get(p0, jj);
                float a1 = f4_get(p1, jj);
                float a2 = f4_get(p2, jj);
                float a3 = f4_get(p3, jj);
                o[0][0] += a0 * vv.x; o[0][1] += a0 * vv.y; o[0][2] += a0 * vv.z; o[0][3] += a0 * vv.w;
                o[1][0] += a1 * vv.x; o[1][1] += a1 * vv.y; o[1][2] += a1 * vv.z; o[1][3] += a1 * vv.w;
                o[2][0] += a2 * vv.x; o[2][1] += a2 * vv.y; o[2][2] += a2 * vv.z; o[2][3] += a2 * vv.w;
                o[3][0] += a3 * vv.x; o[3][1] += a3 * vv.y; o[3][2] += a3 * vv.z; o[3][3] += a3 * vv.w;
            }
        }

        if (causal && kt == qt) {
            int lack = 0;
            #pragma unroll
            for (int i = 0; i < 4; ++i)
                if (m_i[i] <= -5000.0f) lack = 1;
            if (__syncthreads_or(lack)) limit = NTILES;
        }
    }

    #pragma unroll
    for (int i = 0; i < 4; ++i) {
        float inv = 1.0f / l_i[i];
        float4 r = make_float4(o[i][0] * inv, o[i][1] * inv, o[i][2] * inv, o[i][3] * inv);
        *reinterpret_cast<float4*>(&g_O[(((size_t)bh) * SEQ + q0 + rr + i) * HD + cc]) = r;
    }
}

// ----------------------------------------------------------------------------
extern "C" void kernel_launch(void* const* d_in, const int* in_sizes, int n_in,
                              void* d_out, int out_size)
{
    const float* q    = (const float*)d_in[0];
    const float* k    = (const float*)d_in[1];
    const float* v    = (const float*)d_in[2];
    const int*   mask = (const int*)d_in[3];
    const float* Wq   = (const float*)d_in[4];
    const float* Wk   = (const float*)d_in[5];
    const float* Wv   = (const float*)d_in[6];
    const float* Wo   = (const float*)d_in[7];
    const int*   mfut = (const int*)d_in[8];
    float* out = (float*)d_out;

    const int flash_smem = 3 * 64 * 64 * (int)sizeof(float);  // 48KB

    static bool attr_set = false;
    if (!attr_set) {
        cudaFuncSetAttribute(qkv_proj_kernel, cudaFuncAttributeMaxDynamicSharedMemorySize, GEMM_SMEM);
        cudaFuncSetAttribute(out_proj_kernel, cudaFuncAttributeMaxDynamicSharedMemorySize, GEMM_SMEM);
        attr_set = true;
    }

    qkv_proj_kernel<<<dim3(DM / 128, MTOT / 128, 3), 256, GEMM_SMEM>>>(q, k, v, Wq, Wk, Wv);
    flash_kernel<<<dim3(SEQ / 64, BH), 256, flash_smem>>>(mask, mfut);
    out_proj_kernel<<<dim3(DM / 128, MTOT / 128), 256, GEMM_SMEM>>>(Wo, out);
}

// round 12
// speedup vs baseline: 1.2460x; 1.2460x over previous
#include <cuda_runtime.h>
#include <cstdint>

// ----------------------------------------------------------------------------
// MultiHeadAttention, fp32 semantics.
// Stage 0: preconvert X,W -> tf32 hi/lo pairs in MMA-fragment-major layout.
// Stage 1: QKV projections via 3xTF32 mma.sync (tensor pipe, zero cvt in loop).
// Stage 2: flash attention Br=Bc=64 (R8-validated, unchanged).
// Stage 3: output projection SIMT SGEMM (R8-validated, unchanged).
// ----------------------------------------------------------------------------

constexpr int BATCH = 2;
constexpr int SEQ   = 2048;
constexpr int DM    = 768;
constexpr int NH    = 12;
constexpr int HD    = 64;
constexpr int BH    = BATCH * NH;   // 24
constexpr int MTOT  = BATCH * SEQ;  // 4096
constexpr int NTILES = SEQ / 64;    // 32
constexpr float NEGV  = -10000.0f;
constexpr float SCALE = 0.125f;

constexpr int KATOMS = DM / 8;      // 96
constexpr int MATOMS = MTOT / 16;   // 256
constexpr int NATOMS = DM / 8;      // 96

__device__ float g_Q[BATCH * NH * SEQ * HD];
__device__ float g_K[BATCH * NH * SEQ * HD];
__device__ float g_V[BATCH * NH * SEQ * HD];
__device__ float g_O[BATCH * NH * SEQ * HD];

// fragment-major split buffers
// A atom (16m x 8k): 256 floats = [hi: lane*4..+3][lo at +128]
// B atom (8k x 8n):  128 floats = [lane*4: b0h,b1h,b0l,b1l]
__device__ __align__(16) float g_Xs[3][KATOMS * MATOMS * 256];
__device__ __align__(16) float g_Ws[3][KATOMS * NATOMS * 128];

__device__ __forceinline__ float f4_get(const float4& v, int j) {
    return j == 0 ? v.x : j == 1 ? v.y : j == 2 ? v.z : v.w;
}
__device__ __forceinline__ uint32_t tf32_bits(float x) {
    uint32_t u;
    asm("cvt.rna.tf32.f32 %0, %1;" : "=r"(u) : "f"(x));
    return u;
}
__device__ __forceinline__ void split_hilo(float x, float& h, float& l) {
    uint32_t hb = tf32_bits(x);
    h = __uint_as_float(hb);
    l = __uint_as_float(tf32_bits(x - h));
}
__device__ __forceinline__ void mma_tf32(float d[4], const uint32_t a[4], const uint32_t b[2]) {
    asm volatile(
        "mma.sync.aligned.m16n8k8.row.col.f32.tf32.tf32.f32 "
        "{%0,%1,%2,%3}, {%4,%5,%6,%7}, {%8,%9}, {%0,%1,%2,%3};"
        : "+f"(d[0]), "+f"(d[1]), "+f"(d[2]), "+f"(d[3])
        : "r"(a[0]), "r"(a[1]), "r"(a[2]), "r"(a[3]), "r"(b[0]), "r"(b[1]));
}

// ----------------------------------------------------------------------------
// Stage 0a: split X (q,k,v) into fragment-major hi/lo atoms.
// One warp per A-atom. grid = (KATOMS*MATOMS/8, 3), 256 threads.
// a0=X[m+gid][k+tig], a1=X[m+gid+8][k+tig], a2=..[tig+4], a3=..
// ----------------------------------------------------------------------------
__global__ void __launch_bounds__(256) pre_x_kernel(
    const float* __restrict__ q, const float* __restrict__ k, const float* __restrict__ v)
{
    const int z = blockIdx.y;
    const float* X = (z == 0) ? q : (z == 1) ? k : v;
    float* dst = g_Xs[z];

    const int wid = threadIdx.x >> 5, lane = threadIdx.x & 31;
    const int atom = blockIdx.x * 8 + wid;     // katom*MATOMS + matom
    const int katom = atom >> 8;               // /256
    const int matom = atom & 255;
    const int gid = lane >> 2, tig = lane & 3;
    const int m = matom * 16, kk = katom * 8;

    float a0 = X[(size_t)(m + gid) * DM + kk + tig];
    float a1 = X[(size_t)(m + gid + 8) * DM + kk + tig];
    float a2 = X[(size_t)(m + gid) * DM + kk + tig + 4];
    float a3 = X[(size_t)(m + gid + 8) * DM + kk + tig + 4];

    float h0, l0, h1, l1, h2, l2, h3, l3;
    split_hilo(a0, h0, l0); split_hilo(a1, h1, l1);
    split_hilo(a2, h2, l2); split_hilo(a3, h3, l3);

    float* base = dst + (size_t)atom * 256;
    *reinterpret_cast<float4*>(base + lane * 4)       = make_float4(h0, h1, h2, h3);
    *reinterpret_cast<float4*>(base + 128 + lane * 4) = make_float4(l0, l1, l2, l3);
}

// ----------------------------------------------------------------------------
// Stage 0b: split W (Wq,Wk,Wv) into fragment-major hi/lo atoms.
// One warp per B-atom. grid = (KATOMS*NATOMS/8, 3), 256 threads.
// b0=W[k+tig][n+gid], b1=W[k+tig+4][n+gid].
// ----------------------------------------------------------------------------
__global__ void __launch_bounds__(256) pre_w_kernel(
    const float* __restrict__ Wq, const float* __restrict__ Wk, const float* __restrict__ Wv)
{
    const int z = blockIdx.y;
    const float* W = (z == 0) ? Wq : (z == 1) ? Wk : Wv;
    float* dst = g_Ws[z];

    const int wid = threadIdx.x >> 5, lane = threadIdx.x & 31;
    const int atom = blockIdx.x * 8 + wid;     // katom*NATOMS + natom
    const int katom = atom / NATOMS;
    const int natom = atom - katom * NATOMS;
    const int gid = lane >> 2, tig = lane & 3;

    float b0 = W[(size_t)(katom * 8 + tig) * DM + natom * 8 + gid];
    float b1 = W[(size_t)(katom * 8 + tig + 4) * DM + natom * 8 + gid];

    float h0, l0, h1, l1;
    split_hilo(b0, h0, l0); split_hilo(b1, h1, l1);

    *reinterpret_cast<float4*>(dst + (size_t)atom * 128 + lane * 4) =
        make_float4(h0, h1, l0, l1);
}

// ----------------------------------------------------------------------------
// Stage 1: QKV projections via 3xTF32 mma.  grid = (6, 32, 3), 256 threads.
// Block 128x128, 8 warps (wm 0..1, wn 0..3), warp tile 64x32.
// smem 64KB: As[4 katom][8 matom][256] + Bs[4 katom][16 natom][128].
// ----------------------------------------------------------------------------
constexpr int QKV_SMEM = 16384 * (int)sizeof(float);   // 64KB

__global__ void __launch_bounds__(256, 2) qkv_mma_kernel()
{
    extern __shared__ float smm[];
    float* As = smm;             // 8192 floats
    float* Bs = smm + 8192;      // 8192 floats

    const int z = blockIdx.z;
    const float* Af = g_Xs[z];
    const float* Bf = g_Ws[z];
    float* out = (z == 0) ? g_Q : (z == 1) ? g_K : g_V;

    const int n0 = blockIdx.x * 128;
    const int m0 = blockIdx.y * 128;
    const int tid = threadIdx.x;
    const int lane = tid & 31;
    const int wid = tid >> 5;
    const int wm = wid >> 2, wn = wid & 3;

    float acc[4][4][4] = {};

    for (int ch = 0; ch < DM / 32; ++ch) {
        // fill: pure float4 copies (data already split + fragment-major)
        #pragma unroll
        for (int kl = 0; kl < 4; ++kl) {
            const int kg = ch * 4 + kl;
            const float4* asrc = reinterpret_cast<const float4*>(
                Af + ((size_t)kg * MATOMS + (m0 >> 4)) * 256);
            float4* adst = reinterpret_cast<float4*>(As + kl * 2048);
            adst[tid * 2]     = asrc[tid * 2];
            adst[tid * 2 + 1] = asrc[tid * 2 + 1];
            const float4* bsrc = reinterpret_cast<const float4*>(
                Bf + ((size_t)kg * NATOMS + (n0 >> 3)) * 128);
            float4* bdst = reinterpret_cast<float4*>(Bs + kl * 2048);
            bdst[tid * 2]     = bsrc[tid * 2];
            bdst[tid * 2 + 1] = bsrc[tid * 2 + 1];
        }
        __syncthreads();

        #pragma unroll
        for (int kk8 = 0; kk8 < 4; ++kk8) {
            float4 b4[4];
            #pragma unroll
            for (int bn = 0; bn < 4; ++bn)
                b4[bn] = *reinterpret_cast<const float4*>(
                    &Bs[kk8 * 2048 + (wn * 4 + bn) * 128 + lane * 4]);
            #pragma unroll
            for (int am = 0; am < 4; ++am) {
                const float* ab = &As[kk8 * 2048 + (wm * 4 + am) * 256];
                float4 h = *reinterpret_cast<const float4*>(ab + lane * 4);
                float4 l = *reinterpret_cast<const float4*>(ab + 128 + lane * 4);
                uint32_t ah[4] = {__float_as_uint(h.x), __float_as_uint(h.y),
                                  __float_as_uint(h.z), __float_as_uint(h.w)};
                uint32_t al[4] = {__float_as_uint(l.x), __float_as_uint(l.y),
                                  __float_as_uint(l.z), __float_as_uint(l.w)};
                #pragma unroll
                for (int bn = 0; bn < 4; ++bn) {
                    uint32_t bh[2] = {__float_as_uint(b4[bn].x), __float_as_uint(b4[bn].y)};
                    uint32_t bl[2] = {__float_as_uint(b4[bn].z), __float_as_uint(b4[bn].w)};
                    mma_tf32(acc[am][bn], ah, bh);
                    mma_tf32(acc[am][bn], ah, bl);
                    mma_tf32(acc[am][bn], al, bh);
                }
            }
        }
        __syncthreads();
    }

    // epilogue -> head-major [B,H,S,64]
    const int r = lane >> 2;
    const int c2 = (lane & 3) * 2;
    #pragma unroll
    for (int am = 0; am < 4; ++am) {
        #pragma unroll
        for (int bn = 0; bn < 4; ++bn) {
            int col = n0 + wn * 32 + bn * 8 + c2;
            int head = col >> 6, d0 = col & 63;
            int mA = m0 + wm * 64 + am * 16 + r;
            int bb = mA >> 11, ss = mA & (SEQ - 1);
            *reinterpret_cast<float2*>(&out[(((size_t)(bb * NH + head)) * SEQ + ss) * HD + d0]) =
                make_float2(acc[am][bn][0], acc[am][bn][1]);
            int mB = mA + 8;
            int bb2 = mB >> 11, ss2 = mB & (SEQ - 1);
            *reinterpret_cast<float2*>(&out[(((size_t)(bb2 * NH + head)) * SEQ + ss2) * HD + d0]) =
                make_float2(acc[am][bn][2], acc[am][bn][3]);
        }
    }
}

// ----------------------------------------------------------------------------
// Stage 2: flash attention (R8-validated, unchanged).
// ----------------------------------------------------------------------------
__global__ void __launch_bounds__(256) flash_kernel(
    const int* __restrict__ attn_mask, const int* __restrict__ mask_future)
{
    extern __shared__ float sm[];
    float* Qt = sm;
    float* Kt = sm + 4096;
    float* Vs = sm + 8192;
    float* Ps = Kt;

    const int tid = threadIdx.x;
    const int tx = tid & 15, ty = tid >> 4;
    const int rr = ty * 4, cc = tx * 4;
    const int qt = (int)gridDim.x - 1 - (int)blockIdx.x;
    const int bh = blockIdx.y;
    const int b  = bh / NH;
    const int q0 = qt * 64;
    const bool causal = (mask_future[0] != 0);

    {
        int j = tid & 63;
        int dq = (tid >> 6) * 16;
        #pragma unroll
        for (int qd = 0; qd < 4; ++qd) {
            int d = dq + qd * 4;
            float4 qv = *reinterpret_cast<const float4*>(
                &g_Q[(((size_t)bh) * SEQ + q0 + j) * HD + d]);
            Qt[(d + 0) * 64 + j] = qv.x;
            Qt[(d + 1) * 64 + j] = qv.y;
            Qt[(d + 2) * 64 + j] = qv.z;
            Qt[(d + 3) * 64 + j] = qv.w;
        }
    }

    float m_i[4], l_i[4], o[4][4];
    #pragma unroll
    for (int i = 0; i < 4; ++i) {
        m_i[i] = -1e30f;
        l_i[i] = 0.0f;
        o[i][0] = o[i][1] = o[i][2] = o[i][3] = 0.0f;
    }

    int limit = causal ? (qt + 1) : NTILES;

    for (int kt = 0; kt < NTILES; ++kt) {
        if (kt >= limit) break;
        const int k0 = kt * 64;
        __syncthreads();

        {
            int j = tid & 63;
            int dq = (tid >> 6) * 16;
            #pragma unroll
            for (int qd = 0; qd < 4; ++qd) {
                int d = dq + qd * 4;
                float4 kv = *reinterpret_cast<const float4*>(
                    &g_K[(((size_t)bh) * SEQ + k0 + j) * HD + d]);
                Kt[(d + 0) * 64 + j] = kv.x;
                Kt[(d + 1) * 64 + j] = kv.y;
                Kt[(d + 2) * 64 + j] = kv.z;
                Kt[(d + 3) * 64 + j] = kv.w;
            }
        }
        #pragma unroll
        for (int qd = 0; qd < 4; ++qd) {
            int fi = tid + qd * 256;
            int row = fi >> 4;
            int col = (fi & 15) * 4;
            *reinterpret_cast<float4*>(&Vs[row * 64 + col]) =
                *reinterpret_cast<const float4*>(&g_V[(((size_t)bh) * SEQ + k0 + row) * HD + col]);
        }
        int mk[4];
        #pragma unroll
        for (int j = 0; j < 4; ++j)
            mk[j] = attn_mask[b * SEQ + k0 + cc + j];
        __syncthreads();

        float sacc[4][4] = {};
        #pragma unroll 16
        for (int d = 0; d < 64; ++d) {
            float4 qa = *reinterpret_cast<float4*>(&Qt[d * 64 + rr]);
            float4 kb = *reinterpret_cast<float4*>(&Kt[d * 64 + cc]);
            sacc[0][0] += qa.x * kb.x; sacc[0][1] += qa.x * kb.y; sacc[0][2] += qa.x * kb.z; sacc[0][3] += qa.x * kb.w;
            sacc[1][0] += qa.y * kb.x; sacc[1][1] += qa.y * kb.y; sacc[1][2] += qa.y * kb.z; sacc[1][3] += qa.y * kb.w;
            sacc[2][0] += qa.z * kb.x; sacc[2][1] += qa.z * kb.y; sacc[2][2] += qa.z * kb.z; sacc[2][3] += qa.z * kb.w;
            sacc[3][0] += qa.w * kb.x; sacc[3][1] += qa.w * kb.y; sacc[3][2] += qa.w * kb.z; sacc[3][3] += qa.w * kb.w;
        }
        __syncthreads();

        #pragma unroll
        for (int i = 0; i < 4; ++i) {
            int ig = q0 + rr + i;
            #pragma unroll
            for (int j = 0; j < 4; ++j) {
                int jg = k0 + cc + j;
                float sv = sacc[i][j] * SCALE;
                if (causal && jg > ig) sv += NEGV;
                if (mk[j] == 0) sv = NEGV;
                sacc[i][j] = sv;
            }
        }

        #pragma unroll
        for (int i = 0; i < 4; ++i) {
            float tm = fmaxf(fmaxf(sacc[i][0], sacc[i][1]), fmaxf(sacc[i][2], sacc[i][3]));
            #pragma unroll
            for (int off = 8; off; off >>= 1)
                tm = fmaxf(tm, __shfl_xor_sync(0xffffffffu, tm, off));
            float mnew = fmaxf(m_i[i], tm);
            float alpha = __expf(m_i[i] - mnew);
            float ps = 0.0f;
            #pragma unroll
            for (int j = 0; j < 4; ++j) {
                float p = __expf(sacc[i][j] - mnew);
                sacc[i][j] = p;
                ps += p;
            }
            #pragma unroll
            for (int off = 8; off; off >>= 1)
                ps += __shfl_xor_sync(0xffffffffu, ps, off);
            l_i[i] = l_i[i] * alpha + ps;
            m_i[i] = mnew;
            o[i][0] *= alpha; o[i][1] *= alpha; o[i][2] *= alpha; o[i][3] *= alpha;
        }

        #pragma unroll
        for (int i = 0; i < 4; ++i)
            *reinterpret_cast<float4*>(&Ps[(rr + i) * 64 + cc]) =
                make_float4(sacc[i][0], sacc[i][1], sacc[i][2], sacc[i][3]);
        __syncthreads();

        #pragma unroll 8
        for (int j4 = 0; j4 < 64; j4 += 4) {
            float4 p0 = *reinterpret_cast<float4*>(&Ps[(rr + 0) * 64 + j4]);
            float4 p1 = *reinterpret_cast<float4*>(&Ps[(rr + 1) * 64 + j4]);
            float4 p2 = *reinterpret_cast<float4*>(&Ps[(rr + 2) * 64 + j4]);
            float4 p3 = *reinterpret_cast<float4*>(&Ps[(rr + 3) * 64 + j4]);
            #pragma unroll
            for (int jj = 0; jj < 4; ++jj) {
                float4 vv = *reinterpret_cast<float4*>(&Vs[(j4 + jj) * 64 + cc]);
                float a0 = f4_get(p0, jj);
                float a1 = f4_get(p1, jj);
                float a2 = f4_get(p2, jj);
                float a3 = f4_get(p3, jj);
                o[0][0] += a0 * vv.x; o[0][1] += a0 * vv.y; o[0][2] += a0 * vv.z; o[0][3] += a0 * vv.w;
                o[1][0] += a1 * vv.x; o[1][1] += a1 * vv.y; o[1][2] += a1 * vv.z; o[1][3] += a1 * vv.w;
                o[2][0] += a2 * vv.x; o[2][1] += a2 * vv.y; o[2][2] += a2 * vv.z; o[2][3] += a2 * vv.w;
                o[3][0] += a3 * vv.x; o[3][1] += a3 * vv.y; o[3][2] += a3 * vv.z; o[3][3] += a3 * vv.w;
            }
        }

        if (causal && kt == qt) {
            int lack = 0;
            #pragma unroll
            for (int i = 0; i < 4; ++i)
                if (m_i[i] <= -5000.0f) lack = 1;
            if (__syncthreads_or(lack)) limit = NTILES;
        }
    }

    #pragma unroll
    for (int i = 0; i < 4; ++i) {
        float inv = 1.0f / l_i[i];
        float4 r = make_float4(o[i][0] * inv, o[i][1] * inv, o[i][2] * inv, o[i][3] * inv);
        *reinterpret_cast<float4*>(&g_O[(((size_t)bh) * SEQ + q0 + rr + i) * HD + cc]) = r;
    }
}

// ----------------------------------------------------------------------------
// Stage 3: output projection (R8-validated SIMT, unchanged).
// grid = (DM/64, MTOT/128), 256 threads.
// ----------------------------------------------------------------------------
__global__ void __launch_bounds__(256) out_proj_kernel(
    const float* __restrict__ Wo, float* __restrict__ out)
{
    __shared__ float As[16 * 128];
    __shared__ float Bs[16 * 64];

    const int n0 = blockIdx.x * 64;
    const int m0 = blockIdx.y * 128;
    const int tid = threadIdx.x;
    const int tx = tid & 15, ty = tid >> 4;

    const int am = tid >> 1;
    const int ak = (tid & 1) * 8;
    const int brow = tid >> 4;
    const int bcol = (tid & 15) * 4;

    const int m = m0 + am;
    const int bb = m >> 11;
    const int ss = m & (SEQ - 1);

    float acc[8][4] = {};

    for (int k0 = 0; k0 < DM; k0 += 16) {
        int kidx = k0 + ak;
        int h = kidx >> 6, dd = kidx & 63;
        const float* src = &g_O[(((size_t)(bb * NH + h)) * SEQ + ss) * HD + dd];
        float4 a0 = *reinterpret_cast<const float4*>(src);
        float4 a1 = *reinterpret_cast<const float4*>(src + 4);
        As[(ak + 0) * 128 + am] = a0.x;
        As[(ak + 1) * 128 + am] = a0.y;
        As[(ak + 2) * 128 + am] = a0.z;
        As[(ak + 3) * 128 + am] = a0.w;
        As[(ak + 4) * 128 + am] = a1.x;
        As[(ak + 5) * 128 + am] = a1.y;
        As[(ak + 6) * 128 + am] = a1.z;
        As[(ak + 7) * 128 + am] = a1.w;
        *reinterpret_cast<float4*>(&Bs[brow * 64 + bcol]) =
            *reinterpret_cast<const float4*>(&Wo[(size_t)(k0 + brow) * DM + n0 + bcol]);
        __syncthreads();

        #pragma unroll
        for (int kk = 0; kk < 16; ++kk) {
            float4 ra0 = *reinterpret_cast<float4*>(&As[kk * 128 + ty * 8]);
            float4 ra1 = *reinterpret_cast<float4*>(&As[kk * 128 + ty * 8 + 4]);
            float4 b   = *reinterpret_cast<float4*>(&Bs[kk * 64 + tx * 4]);
            float ar[8] = {ra0.x, ra0.y, ra0.z, ra0.w, ra1.x, ra1.y, ra1.z, ra1.w};
            #pragma unroll
            for (int i = 0; i < 8; ++i) {
                acc[i][0] += ar[i] * b.x;
                acc[i][1] += ar[i] * b.y;
                acc[i][2] += ar[i] * b.z;
                acc[i][3] += ar[i] * b.w;
            }
        }
        __syncthreads();
    }

    #pragma unroll
    for (int i = 0; i < 8; ++i) {
        int mm = m0 + ty * 8 + i;
        *reinterpret_cast<float4*>(&out[(size_t)mm * DM + n0 + tx * 4]) =
            make_float4(acc[i][0], acc[i][1], acc[i][2], acc[i][3]);
    }
}

// ----------------------------------------------------------------------------
extern "C" void kernel_launch(void* const* d_in, const int* in_sizes, int n_in,
                              void* d_out, int out_size)
{
    const float* q    = (const float*)d_in[0];
    const float* k    = (const float*)d_in[1];
    const float* v    = (const float*)d_in[2];
    const int*   mask = (const int*)d_in[3];
    const float* Wq   = (const float*)d_in[4];
    const float* Wk   = (const float*)d_in[5];
    const float* Wv   = (const float*)d_in[6];
    const float* Wo   = (const float*)d_in[7];
    const int*   mfut = (const int*)d_in[8];
    float* out = (float*)d_out;

    const int flash_smem = 3 * 64 * 64 * (int)sizeof(float);  // 48KB

    static bool attr_set = false;
    if (!attr_set) {
        cudaFuncSetAttribute(qkv_mma_kernel, cudaFuncAttributeMaxDynamicSharedMemorySize, QKV_SMEM);
        attr_set = true;
    }

    pre_x_kernel<<<dim3(KATOMS * MATOMS / 8, 3), 256>>>(q, k, v);
    pre_w_kernel<<<dim3(KATOMS * NATOMS / 8, 3), 256>>>(Wq, Wk, Wv);
    qkv_mma_kernel<<<dim3(DM / 128, MTOT / 128, 3), 256, QKV_SMEM>>>();
    flash_kernel<<<dim3(SEQ / 64, BH), 256, flash_smem>>>(mask, mfut);
    out_proj_kernel<<<dim3(DM / 64, MTOT / 128), 256>>>(Wo, out);
}

// round 13
// speedup vs baseline: 1.4612x; 1.1727x over previous
#include <cuda_runtime.h>
#include <cstdint>

// ----------------------------------------------------------------------------
// MultiHeadAttention, fp32 semantics.
// Stage 0: preconvert X,W -> tf32 hi/lo fragment-major (R12-validated).
// Stage 1: QKV projections via 3xTF32 mma.sync (R12-validated).
// Stage 2: flash attention Br=128/Bc=64 via TF32 mma.sync (NEW).
// Stage 3: output projection SIMT SGEMM (R8-validated).
// ----------------------------------------------------------------------------

constexpr int BATCH = 2;
constexpr int SEQ   = 2048;
constexpr int DM    = 768;
constexpr int NH    = 12;
constexpr int HD    = 64;
constexpr int BH    = BATCH * NH;   // 24
constexpr int MTOT  = BATCH * SEQ;  // 4096
constexpr int NTILES = SEQ / 64;    // 32
constexpr int QTILES = SEQ / 128;   // 16
constexpr float NEGV  = -10000.0f;
constexpr float SCALE = 0.125f;

constexpr int KATOMS = DM / 8;      // 96
constexpr int MATOMS = MTOT / 16;   // 256
constexpr int NATOMS = DM / 8;      // 96

__device__ float g_Q[BATCH * NH * SEQ * HD];
__device__ float g_K[BATCH * NH * SEQ * HD];
__device__ float g_V[BATCH * NH * SEQ * HD];
__device__ float g_O[BATCH * NH * SEQ * HD];

__device__ __align__(16) float g_Xs[3][KATOMS * MATOMS * 256];
__device__ __align__(16) float g_Ws[3][KATOMS * NATOMS * 128];

__device__ __forceinline__ uint32_t tf32_bits(float x) {
    uint32_t u;
    asm("cvt.rna.tf32.f32 %0, %1;" : "=r"(u) : "f"(x));
    return u;
}
__device__ __forceinline__ void split_hilo(float x, float& h, float& l) {
    uint32_t hb = tf32_bits(x);
    h = __uint_as_float(hb);
    l = __uint_as_float(tf32_bits(x - h));
}
__device__ __forceinline__ void mma_tf32(float d[4], const uint32_t a[4], const uint32_t b[2]) {
    asm volatile(
        "mma.sync.aligned.m16n8k8.row.col.f32.tf32.tf32.f32 "
        "{%0,%1,%2,%3}, {%4,%5,%6,%7}, {%8,%9}, {%0,%1,%2,%3};"
        : "+f"(d[0]), "+f"(d[1]), "+f"(d[2]), "+f"(d[3])
        : "r"(a[0]), "r"(a[1]), "r"(a[2]), "r"(a[3]), "r"(b[0]), "r"(b[1]));
}

// ----------------------------------------------------------------------------
// Stage 0a/0b: preconvert (R12-validated, unchanged).
// ----------------------------------------------------------------------------
__global__ void __launch_bounds__(256) pre_x_kernel(
    const float* __restrict__ q, const float* __restrict__ k, const float* __restrict__ v)
{
    const int z = blockIdx.y;
    const float* X = (z == 0) ? q : (z == 1) ? k : v;
    float* dst = g_Xs[z];

    const int wid = threadIdx.x >> 5, lane = threadIdx.x & 31;
    const int atom = blockIdx.x * 8 + wid;
    const int katom = atom >> 8;
    const int matom = atom & 255;
    const int gid = lane >> 2, tig = lane & 3;
    const int m = matom * 16, kk = katom * 8;

    float a0 = X[(size_t)(m + gid) * DM + kk + tig];
    float a1 = X[(size_t)(m + gid + 8) * DM + kk + tig];
    float a2 = X[(size_t)(m + gid) * DM + kk + tig + 4];
    float a3 = X[(size_t)(m + gid + 8) * DM + kk + tig + 4];

    float h0, l0, h1, l1, h2, l2, h3, l3;
    split_hilo(a0, h0, l0); split_hilo(a1, h1, l1);
    split_hilo(a2, h2, l2); split_hilo(a3, h3, l3);

    float* base = dst + (size_t)atom * 256;
    *reinterpret_cast<float4*>(base + lane * 4)       = make_float4(h0, h1, h2, h3);
    *reinterpret_cast<float4*>(base + 128 + lane * 4) = make_float4(l0, l1, l2, l3);
}

__global__ void __launch_bounds__(256) pre_w_kernel(
    const float* __restrict__ Wq, const float* __restrict__ Wk, const float* __restrict__ Wv)
{
    const int z = blockIdx.y;
    const float* W = (z == 0) ? Wq : (z == 1) ? Wk : Wv;
    float* dst = g_Ws[z];

    const int wid = threadIdx.x >> 5, lane = threadIdx.x & 31;
    const int atom = blockIdx.x * 8 + wid;
    const int katom = atom / NATOMS;
    const int natom = atom - katom * NATOMS;
    const int gid = lane >> 2, tig = lane & 3;

    float b0 = W[(size_t)(katom * 8 + tig) * DM + natom * 8 + gid];
    float b1 = W[(size_t)(katom * 8 + tig + 4) * DM + natom * 8 + gid];

    float h0, l0, h1, l1;
    split_hilo(b0, h0, l0); split_hilo(b1, h1, l1);

    *reinterpret_cast<float4*>(dst + (size_t)atom * 128 + lane * 4) =
        make_float4(h0, h1, l0, l1);
}

// ----------------------------------------------------------------------------
// Stage 1: QKV projections via 3xTF32 mma (R12-validated, unchanged).
// ----------------------------------------------------------------------------
constexpr int QKV_SMEM = 16384 * (int)sizeof(float);   // 64KB

__global__ void __launch_bounds__(256, 2) qkv_mma_kernel()
{
    extern __shared__ float smm[];
    float* As = smm;
    float* Bs = smm + 8192;

    const int z = blockIdx.z;
    const float* Af = g_Xs[z];
    const float* Bf = g_Ws[z];
    float* out = (z == 0) ? g_Q : (z == 1) ? g_K : g_V;

    const int n0 = blockIdx.x * 128;
    const int m0 = blockIdx.y * 128;
    const int tid = threadIdx.x;
    const int lane = tid & 31;
    const int wid = tid >> 5;
    const int wm = wid >> 2, wn = wid & 3;

    float acc[4][4][4] = {};

    for (int ch = 0; ch < DM / 32; ++ch) {
        #pragma unroll
        for (int kl = 0; kl < 4; ++kl) {
            const int kg = ch * 4 + kl;
            const float4* asrc = reinterpret_cast<const float4*>(
                Af + ((size_t)kg * MATOMS + (m0 >> 4)) * 256);
            float4* adst = reinterpret_cast<float4*>(As + kl * 2048);
            adst[tid * 2]     = asrc[tid * 2];
            adst[tid * 2 + 1] = asrc[tid * 2 + 1];
            const float4* bsrc = reinterpret_cast<const float4*>(
                Bf + ((size_t)kg * NATOMS + (n0 >> 3)) * 128);
            float4* bdst = reinterpret_cast<float4*>(Bs + kl * 2048);
            bdst[tid * 2]     = bsrc[tid * 2];
            bdst[tid * 2 + 1] = bsrc[tid * 2 + 1];
        }
        __syncthreads();

        #pragma unroll
        for (int kk8 = 0; kk8 < 4; ++kk8) {
            float4 b4[4];
            #pragma unroll
            for (int bn = 0; bn < 4; ++bn)
                b4[bn] = *reinterpret_cast<const float4*>(
                    &Bs[kk8 * 2048 + (wn * 4 + bn) * 128 + lane * 4]);
            #pragma unroll
            for (int am = 0; am < 4; ++am) {
                const float* ab = &As[kk8 * 2048 + (wm * 4 + am) * 256];
                float4 h = *reinterpret_cast<const float4*>(ab + lane * 4);
                float4 l = *reinterpret_cast<const float4*>(ab + 128 + lane * 4);
                uint32_t ah[4] = {__float_as_uint(h.x), __float_as_uint(h.y),
                                  __float_as_uint(h.z), __float_as_uint(h.w)};
                uint32_t al[4] = {__float_as_uint(l.x), __float_as_uint(l.y),
                                  __float_as_uint(l.z), __float_as_uint(l.w)};
                #pragma unroll
                for (int bn = 0; bn < 4; ++bn) {
                    uint32_t bh[2] = {__float_as_uint(b4[bn].x), __float_as_uint(b4[bn].y)};
                    uint32_t bl[2] = {__float_as_uint(b4[bn].z), __float_as_uint(b4[bn].w)};
                    mma_tf32(acc[am][bn], ah, bh);
                    mma_tf32(acc[am][bn], ah, bl);
                    mma_tf32(acc[am][bn], al, bh);
                }
            }
        }
        __syncthreads();
    }

    const int r = lane >> 2;
    const int c2 = (lane & 3) * 2;
    #pragma unroll
    for (int am = 0; am < 4; ++am) {
        #pragma unroll
        for (int bn = 0; bn < 4; ++bn) {
            int col = n0 + wn * 32 + bn * 8 + c2;
            int head = col >> 6, d0 = col & 63;
            int mA = m0 + wm * 64 + am * 16 + r;
            int bb = mA >> 11, ss = mA & (SEQ - 1);
            *reinterpret_cast<float2*>(&out[(((size_t)(bb * NH + head)) * SEQ + ss) * HD + d0]) =
                make_float2(acc[am][bn][0], acc[am][bn][1]);
            int mB = mA + 8;
            int bb2 = mB >> 11, ss2 = mB & (SEQ - 1);
            *reinterpret_cast<float2*>(&out[(((size_t)(bb2 * NH + head)) * SEQ + ss2) * HD + d0]) =
                make_float2(acc[am][bn][2], acc[am][bn][3]);
        }
    }
}

// ----------------------------------------------------------------------------
// Stage 2: flash attention via TF32 mma.  grid = (QTILES, BH), 256 threads.
// Br=128, Bc=64. Warp w owns q-rows [w*16, w*16+16), all 64 keys.
// smem: Qf (unsplit A-frags, 8192) | Kf (hi/lo B-frags, 8192; becomes P) |
//       Vf (hi/lo B-frags, 8192) | msk (64 ints).
// ----------------------------------------------------------------------------
constexpr int FL_SMEM = (3 * 8192 + 64) * (int)sizeof(float);  // 98560 B

__global__ void __launch_bounds__(256, 2) flash_kernel(
    const int* __restrict__ attn_mask, const int* __restrict__ mask_future)
{
    extern __shared__ float sm[];
    float* Qf = sm;            // 8192 floats: atom(ma,ka) at (ma*8+ka)*128
    float* Kf = sm + 8192;     // 8192: atom(na,ka) hi/lo packed; reused as P
    float* Vf = sm + 16384;    // 8192: atom(nd,kk) hi/lo packed
    float* Pf = Kf;
    int* msk = reinterpret_cast<int*>(sm + 24576);

    const int tid = threadIdx.x;
    const int lane = tid & 31;
    const int w = tid >> 5;
    const int gid = lane >> 2, tig = lane & 3;

    const int qtb = QTILES - 1 - (int)blockIdx.x;   // long blocks first
    const int bh = blockIdx.y;
    const int batch = bh / NH;
    const int q0 = qtb * 128;
    const bool causal = (mask_future[0] != 0);

    const int ig0 = q0 + w * 16 + gid;
    const int ig1 = ig0 + 8;

    // ---- Q fill: warp w -> atoms (w, ka), pre-scaled by 1/8 (exact) ----
    {
        const float* Qg = &g_Q[((size_t)bh * SEQ + q0 + w * 16) * HD];
        #pragma unroll
        for (int ka = 0; ka < 8; ++ka) {
            int col = ka * 8 + tig;
            float a0 = Qg[(size_t)gid * HD + col] * SCALE;
            float a1 = Qg[(size_t)(gid + 8) * HD + col] * SCALE;
            float a2 = Qg[(size_t)gid * HD + col + 4] * SCALE;
            float a3 = Qg[(size_t)(gid + 8) * HD + col + 4] * SCALE;
            *reinterpret_cast<float4*>(&Qf[(w * 8 + ka) * 128 + lane * 4]) =
                make_float4(a0, a1, a2, a3);
        }
    }

    float oacc[8][4] = {};
    float m0 = -1e30f, m1 = -1e30f, l0 = 0.0f, l1 = 0.0f;

    int limit = causal ? (2 * qtb + 2) : NTILES;
    const int limit0 = limit;

    for (int kt = 0; kt < NTILES; ++kt) {
        if (kt >= limit) break;
        const int k0 = kt * 64;
        __syncthreads();   // prior GEMM2 reads of Pf/Vf done before refill

        // ---- K fill: warp w -> atoms (na=w, ka), split hi/lo ----
        {
            const float* Kg = &g_K[((size_t)bh * SEQ + k0 + w * 8 + gid) * HD];
            #pragma unroll
            for (int ka = 0; ka < 8; ++ka) {
                int d = ka * 8 + tig;
                float h0, lo0, h1, lo1;
                split_hilo(Kg[d], h0, lo0);
                split_hilo(Kg[d + 4], h1, lo1);
                *reinterpret_cast<float4*>(&Kf[(w * 8 + ka) * 128 + lane * 4]) =
                    make_float4(h0, h1, lo0, lo1);
            }
        }
        // ---- V fill: warp w -> atoms (nd=w, kk), split hi/lo ----
        {
            #pragma unroll
            for (int kk = 0; kk < 8; ++kk) {
                const float* Vg = &g_V[((size_t)bh * SEQ + k0 + kk * 8 + tig) * HD + w * 8 + gid];
                float h0, lo0, h1, lo1;
                split_hilo(Vg[0], h0, lo0);
                split_hilo(Vg[4 * HD], h1, lo1);
                *reinterpret_cast<float4*>(&Vf[(w * 8 + kk) * 128 + lane * 4]) =
                    make_float4(h0, h1, lo0, lo1);
            }
        }
        if (tid < 64) msk[tid] = attn_mask[batch * SEQ + k0 + tid];
        __syncthreads();

        // ---- GEMM1: S = (Q*s) K^T, 3xTF32 ----
        float sacc[8][4] = {};
        #pragma unroll
        for (int ka = 0; ka < 8; ++ka) {
            float4 qf = *reinterpret_cast<const float4*>(&Qf[(w * 8 + ka) * 128 + lane * 4]);
            uint32_t ah[4], al[4];
            {
                float h, l;
                split_hilo(qf.x, h, l); ah[0] = __float_as_uint(h); al[0] = __float_as_uint(l);
                split_hilo(qf.y, h, l); ah[1] = __float_as_uint(h); al[1] = __float_as_uint(l);
                split_hilo(qf.z, h, l); ah[2] = __float_as_uint(h); al[2] = __float_as_uint(l);
                split_hilo(qf.w, h, l); ah[3] = __float_as_uint(h); al[3] = __float_as_uint(l);
            }
            #pragma unroll
            for (int na = 0; na < 8; ++na) {
                float4 kf = *reinterpret_cast<const float4*>(&Kf[(na * 8 + ka) * 128 + lane * 4]);
                uint32_t bh2[2] = {__float_as_uint(kf.x), __float_as_uint(kf.y)};
                uint32_t bl2[2] = {__float_as_uint(kf.z), __float_as_uint(kf.w)};
                mma_tf32(sacc[na], ah, bh2);
                mma_tf32(sacc[na], ah, bl2);
                mma_tf32(sacc[na], al, bh2);
            }
        }

        // ---- masks (causal ADD, pad SET) + online softmax ----
        float mx0 = -1e30f, mx1 = -1e30f;
        #pragma unroll
        for (int na = 0; na < 8; ++na) {
            int j0 = na * 8 + 2 * tig, j1 = j0 + 1;
            int jg0 = k0 + j0, jg1 = k0 + j1;
            float s0 = sacc[na][0], s1 = sacc[na][1];
            float s2 = sacc[na][2], s3 = sacc[na][3];
            if (causal) {
                if (jg0 > ig0) s0 += NEGV;
                if (jg1 > ig0) s1 += NEGV;
                if (jg0 > ig1) s2 += NEGV;
                if (jg1 > ig1) s3 += NEGV;
            }
            if (msk[j0] == 0) { s0 = NEGV; s2 = NEGV; }
            if (msk[j1] == 0) { s1 = NEGV; s3 = NEGV; }
            sacc[na][0] = s0; sacc[na][1] = s1;
            sacc[na][2] = s2; sacc[na][3] = s3;
            mx0 = fmaxf(mx0, fmaxf(s0, s1));
            mx1 = fmaxf(mx1, fmaxf(s2, s3));
        }
        mx0 = fmaxf(mx0, __shfl_xor_sync(0xffffffffu, mx0, 1));
        mx0 = fmaxf(mx0, __shfl_xor_sync(0xffffffffu, mx0, 2));
        mx1 = fmaxf(mx1, __shfl_xor_sync(0xffffffffu, mx1, 1));
        mx1 = fmaxf(mx1, __shfl_xor_sync(0xffffffffu, mx1, 2));

        float mn0 = fmaxf(m0, mx0), mn1 = fmaxf(m1, mx1);
        float alpha0 = __expf(m0 - mn0), alpha1 = __expf(m1 - mn1);
        float sum0 = 0.0f, sum1 = 0.0f;
        #pragma unroll
        for (int na = 0; na < 8; ++na) {
            float p0 = __expf(sacc[na][0] - mn0);
            float p1 = __expf(sacc[na][1] - mn0);
            float p2 = __expf(sacc[na][2] - mn1);
            float p3 = __expf(sacc[na][3] - mn1);
            sacc[na][0] = p0; sacc[na][1] = p1;
            sacc[na][2] = p2; sacc[na][3] = p3;
            sum0 += p0 + p1;
            sum1 += p2 + p3;
        }
        sum0 += __shfl_xor_sync(0xffffffffu, sum0, 1);
        sum0 += __shfl_xor_sync(0xffffffffu, sum0, 2);
        sum1 += __shfl_xor_sync(0xffffffffu, sum1, 1);
        sum1 += __shfl_xor_sync(0xffffffffu, sum1, 2);
        l0 = l0 * alpha0 + sum0;
        l1 = l1 * alpha1 + sum1;
        m0 = mn0; m1 = mn1;
        #pragma unroll
        for (int na = 0; na < 8; ++na) {
            oacc[na][0] *= alpha0; oacc[na][1] *= alpha0;
            oacc[na][2] *= alpha1; oacc[na][3] *= alpha1;
        }

        __syncthreads();   // all warps done reading Kf before P overwrites it

        // ---- P scatter into A-fragment layout (rna tf32), own atoms only ----
        {
            const int c0 = 2 * tig, c1 = c0 + 1;
            const int s0i = (gid * 4 + (c0 & 3)) * 4 + ((c0 >> 2) << 1);
            const int s1i = (gid * 4 + (c1 & 3)) * 4 + ((c1 >> 2) << 1);
            #pragma unroll
            for (int na = 0; na < 8; ++na) {
                float* base = &Pf[(w * 8 + na) * 128];
                base[s0i]     = __uint_as_float(tf32_bits(sacc[na][0]));
                base[s1i]     = __uint_as_float(tf32_bits(sacc[na][1]));
                base[s0i + 1] = __uint_as_float(tf32_bits(sacc[na][2]));
                base[s1i + 1] = __uint_as_float(tf32_bits(sacc[na][3]));
            }
        }
        __syncwarp();

        // ---- GEMM2: O += P V, P single tf32, V 2xTF32 ----
        #pragma unroll
        for (int ka = 0; ka < 8; ++ka) {
            float4 pf = *reinterpret_cast<const float4*>(&Pf[(w * 8 + ka) * 128 + lane * 4]);
            uint32_t pa[4] = {__float_as_uint(pf.x), __float_as_uint(pf.y),
                              __float_as_uint(pf.z), __float_as_uint(pf.w)};
            #pragma unroll
            for (int na = 0; na < 8; ++na) {
                float4 vf = *reinterpret_cast<const float4*>(&Vf[(na * 8 + ka) * 128 + lane * 4]);
                uint32_t vh[2] = {__float_as_uint(vf.x), __float_as_uint(vf.y)};
                uint32_t vl[2] = {__float_as_uint(vf.z), __float_as_uint(vf.w)};
                mma_tf32(oacc[na], pa, vh);
                mma_tf32(oacc[na], pa, vl);
            }
        }

        // ---- all-padded rows attend to future keys (reference semantics) ----
        if (causal && kt == limit0 - 1 && limit0 != NTILES) {
            int lack = (m0 <= -5000.0f || m1 <= -5000.0f) ? 1 : 0;
            if (__syncthreads_or(lack)) limit = NTILES;
        }
    }

    // ---- epilogue: normalize, store head-major ----
    float il0 = 1.0f / l0, il1 = 1.0f / l1;
    #pragma unroll
    for (int na = 0; na < 8; ++na) {
        int col = na * 8 + 2 * tig;
        *reinterpret_cast<float2*>(&g_O[((size_t)bh * SEQ + ig0) * HD + col]) =
            make_float2(oacc[na][0] * il0, oacc[na][1] * il0);
        *reinterpret_cast<float2*>(&g_O[((size_t)bh * SEQ + ig1) * HD + col]) =
            make_float2(oacc[na][2] * il1, oacc[na][3] * il1);
    }
}

// ----------------------------------------------------------------------------
// Stage 3: output projection (R8-validated SIMT, unchanged).
// ----------------------------------------------------------------------------
__global__ void __launch_bounds__(256) out_proj_kernel(
    const float* __restrict__ Wo, float* __restrict__ out)
{
    __shared__ float As[16 * 128];
    __shared__ float Bs[16 * 64];

    const int n0 = blockIdx.x * 64;
    const int m0 = blockIdx.y * 128;
    const int tid = threadIdx.x;
    const int tx = tid & 15, ty = tid >> 4;

    const int am = tid >> 1;
    const int ak = (tid & 1) * 8;
    const int brow = tid >> 4;
    const int bcol = (tid & 15) * 4;

    const int m = m0 + am;
    const int bb = m >> 11;
    const int ss = m & (SEQ - 1);

    float acc[8][4] = {};

    for (int k0 = 0; k0 < DM; k0 += 16) {
        int kidx = k0 + ak;
        int h = kidx >> 6, dd = kidx & 63;
        const float* src = &g_O[(((size_t)(bb * NH + h)) * SEQ + ss) * HD + dd];
        float4 a0 = *reinterpret_cast<const float4*>(src);
        float4 a1 = *reinterpret_cast<const float4*>(src + 4);
        As[(ak + 0) * 128 + am] = a0.x;
        As[(ak + 1) * 128 + am] = a0.y;
        As[(ak + 2) * 128 + am] = a0.z;
        As[(ak + 3) * 128 + am] = a0.w;
        As[(ak + 4) * 128 + am] = a1.x;
        As[(ak + 5) * 128 + am] = a1.y;
        As[(ak + 6) * 128 + am] = a1.z;
        As[(ak + 7) * 128 + am] = a1.w;
        *reinterpret_cast<float4*>(&Bs[brow * 64 + bcol]) =
            *reinterpret_cast<const float4*>(&Wo[(size_t)(k0 + brow) * DM + n0 + bcol]);
        __syncthreads();

        #pragma unroll
        for (int kk = 0; kk < 16; ++kk) {
            float4 ra0 = *reinterpret_cast<float4*>(&As[kk * 128 + ty * 8]);
            float4 ra1 = *reinterpret_cast<float4*>(&As[kk * 128 + ty * 8 + 4]);
            float4 b   = *reinterpret_cast<float4*>(&Bs[kk * 64 + tx * 4]);
            float ar[8] = {ra0.x, ra0.y, ra0.z, ra0.w, ra1.x, ra1.y, ra1.z, ra1.w};
            #pragma unroll
            for (int i = 0; i < 8; ++i) {
                acc[i][0] += ar[i] * b.x;
                acc[i][1] += ar[i] * b.y;
                acc[i][2] += ar[i] * b.z;
                acc[i][3] += ar[i] * b.w;
            }
        }
        __syncthreads();
    }

    #pragma unroll
    for (int i = 0; i < 8; ++i) {
        int mm = m0 + ty * 8 + i;
        *reinterpret_cast<float4*>(&out[(size_t)mm * DM + n0 + tx * 4]) =
            make_float4(acc[i][0], acc[i][1], acc[i][2], acc[i][3]);
    }
}

// ----------------------------------------------------------------------------
extern "C" void kernel_launch(void* const* d_in, const int* in_sizes, int n_in,
                              void* d_out, int out_size)
{
    const float* q    = (const float*)d_in[0];
    const float* k    = (const float*)d_in[1];
    const float* v    = (const float*)d_in[2];
    const int*   mask = (const int*)d_in[3];
    const float* Wq   = (const float*)d_in[4];
    const float* Wk   = (const float*)d_in[5];
    const float* Wv   = (const float*)d_in[6];
    const float* Wo   = (const float*)d_in[7];
    const int*   mfut = (const int*)d_in[8];
    float* out = (float*)d_out;

    static bool attr_set = false;
    if (!attr_set) {
        cudaFuncSetAttribute(qkv_mma_kernel, cudaFuncAttributeMaxDynamicSharedMemorySize, QKV_SMEM);
        cudaFuncSetAttribute(flash_kernel, cudaFuncAttributeMaxDynamicSharedMemorySize, FL_SMEM);
        attr_set = true;
    }

    pre_x_kernel<<<dim3(KATOMS * MATOMS / 8, 3), 256>>>(q, k, v);
    pre_w_kernel<<<dim3(KATOMS * NATOMS / 8, 3), 256>>>(Wq, Wk, Wv);
    qkv_mma_kernel<<<dim3(DM / 128, MTOT / 128, 3), 256, QKV_SMEM>>>();
    flash_kernel<<<dim3(QTILES, BH), 256, FL_SMEM>>>(mask, mfut);
    out_proj_kernel<<<dim3(DM / 64, MTOT / 128), 256>>>(Wo, out);
}

// round 14
// speedup vs baseline: 1.6287x; 1.1147x over previous
#include <cuda_runtime.h>
#include <cstdint>

// ----------------------------------------------------------------------------
// MultiHeadAttention, fp32 semantics.
// Stage 0: preconvert X,W -> tf32 hi/lo fragment-major (R12-validated).
// Stage 1: QKV projections via 3xTF32 mma.sync (R12-validated).
// Stage 2: flash attention TF32 mma, shuffle-P transpose, V single-tf32 (NEW).
// Stage 3: output projection SIMT SGEMM (R8-validated).
// ----------------------------------------------------------------------------

constexpr int BATCH = 2;
constexpr int SEQ   = 2048;
constexpr int DM    = 768;
constexpr int NH    = 12;
constexpr int HD    = 64;
constexpr int BH    = BATCH * NH;   // 24
constexpr int MTOT  = BATCH * SEQ;  // 4096
constexpr int NTILES = SEQ / 64;    // 32
constexpr int QTILES = SEQ / 128;   // 16
constexpr float NEGV  = -10000.0f;
constexpr float SCALE = 0.125f;

constexpr int KATOMS = DM / 8;      // 96
constexpr int MATOMS = MTOT / 16;   // 256
constexpr int NATOMS = DM / 8;      // 96

__device__ float g_Q[BATCH * NH * SEQ * HD];
__device__ float g_K[BATCH * NH * SEQ * HD];
__device__ float g_V[BATCH * NH * SEQ * HD];
__device__ float g_O[BATCH * NH * SEQ * HD];

__device__ __align__(16) float g_Xs[3][KATOMS * MATOMS * 256];
__device__ __align__(16) float g_Ws[3][KATOMS * NATOMS * 128];

__device__ __forceinline__ uint32_t tf32_bits(float x) {
    uint32_t u;
    asm("cvt.rna.tf32.f32 %0, %1;" : "=r"(u) : "f"(x));
    return u;
}
__device__ __forceinline__ void split_hilo(float x, float& h, float& l) {
    uint32_t hb = tf32_bits(x);
    h = __uint_as_float(hb);
    l = __uint_as_float(tf32_bits(x - h));
}
__device__ __forceinline__ void mma_tf32(float d[4], const uint32_t a[4], const uint32_t b[2]) {
    asm volatile(
        "mma.sync.aligned.m16n8k8.row.col.f32.tf32.tf32.f32 "
        "{%0,%1,%2,%3}, {%4,%5,%6,%7}, {%8,%9}, {%0,%1,%2,%3};"
        : "+f"(d[0]), "+f"(d[1]), "+f"(d[2]), "+f"(d[3])
        : "r"(a[0]), "r"(a[1]), "r"(a[2]), "r"(a[3]), "r"(b[0]), "r"(b[1]));
}

// ----------------------------------------------------------------------------
// Stage 0a/0b: preconvert (R12-validated, unchanged).
// ----------------------------------------------------------------------------
__global__ void __launch_bounds__(256) pre_x_kernel(
    const float* __restrict__ q, const float* __restrict__ k, const float* __restrict__ v)
{
    const int z = blockIdx.y;
    const float* X = (z == 0) ? q : (z == 1) ? k : v;
    float* dst = g_Xs[z];

    const int wid = threadIdx.x >> 5, lane = threadIdx.x & 31;
    const int atom = blockIdx.x * 8 + wid;
    const int katom = atom >> 8;
    const int matom = atom & 255;
    const int gid = lane >> 2, tig = lane & 3;
    const int m = matom * 16, kk = katom * 8;

    float a0 = X[(size_t)(m + gid) * DM + kk + tig];
    float a1 = X[(size_t)(m + gid + 8) * DM + kk + tig];
    float a2 = X[(size_t)(m + gid) * DM + kk + tig + 4];
    float a3 = X[(size_t)(m + gid + 8) * DM + kk + tig + 4];

    float h0, l0, h1, l1, h2, l2, h3, l3;
    split_hilo(a0, h0, l0); split_hilo(a1, h1, l1);
    split_hilo(a2, h2, l2); split_hilo(a3, h3, l3);

    float* base = dst + (size_t)atom * 256;
    *reinterpret_cast<float4*>(base + lane * 4)       = make_float4(h0, h1, h2, h3);
    *reinterpret_cast<float4*>(base + 128 + lane * 4) = make_float4(l0, l1, l2, l3);
}

__global__ void __launch_bounds__(256) pre_w_kernel(
    const float* __restrict__ Wq, const float* __restrict__ Wk, const float* __restrict__ Wv)
{
    const int z = blockIdx.y;
    const float* W = (z == 0) ? Wq : (z == 1) ? Wk : Wv;
    float* dst = g_Ws[z];

    const int wid = threadIdx.x >> 5, lane = threadIdx.x & 31;
    const int atom = blockIdx.x * 8 + wid;
    const int katom = atom / NATOMS;
    const int natom = atom - katom * NATOMS;
    const int gid = lane >> 2, tig = lane & 3;

    float b0 = W[(size_t)(katom * 8 + tig) * DM + natom * 8 + gid];
    float b1 = W[(size_t)(katom * 8 + tig + 4) * DM + natom * 8 + gid];

    float h0, l0, h1, l1;
    split_hilo(b0, h0, l0); split_hilo(b1, h1, l1);

    *reinterpret_cast<float4*>(dst + (size_t)atom * 128 + lane * 4) =
        make_float4(h0, h1, l0, l1);
}

// ----------------------------------------------------------------------------
// Stage 1: QKV projections via 3xTF32 mma (R12-validated, unchanged).
// ----------------------------------------------------------------------------
constexpr int QKV_SMEM = 16384 * (int)sizeof(float);   // 64KB

__global__ void __launch_bounds__(256, 2) qkv_mma_kernel()
{
    extern __shared__ float smm[];
    float* As = smm;
    float* Bs = smm + 8192;

    const int z = blockIdx.z;
    const float* Af = g_Xs[z];
    const float* Bf = g_Ws[z];
    float* out = (z == 0) ? g_Q : (z == 1) ? g_K : g_V;

    const int n0 = blockIdx.x * 128;
    const int m0 = blockIdx.y * 128;
    const int tid = threadIdx.x;
    const int lane = tid & 31;
    const int wid = tid >> 5;
    const int wm = wid >> 2, wn = wid & 3;

    float acc[4][4][4] = {};

    for (int ch = 0; ch < DM / 32; ++ch) {
        #pragma unroll
        for (int kl = 0; kl < 4; ++kl) {
            const int kg = ch * 4 + kl;
            const float4* asrc = reinterpret_cast<const float4*>(
                Af + ((size_t)kg * MATOMS + (m0 >> 4)) * 256);
            float4* adst = reinterpret_cast<float4*>(As + kl * 2048);
            adst[tid * 2]     = asrc[tid * 2];
            adst[tid * 2 + 1] = asrc[tid * 2 + 1];
            const float4* bsrc = reinterpret_cast<const float4*>(
                Bf + ((size_t)kg * NATOMS + (n0 >> 3)) * 128);
            float4* bdst = reinterpret_cast<float4*>(Bs + kl * 2048);
            bdst[tid * 2]     = bsrc[tid * 2];
            bdst[tid * 2 + 1] = bsrc[tid * 2 + 1];
        }
        __syncthreads();

        #pragma unroll
        for (int kk8 = 0; kk8 < 4; ++kk8) {
            float4 b4[4];
            #pragma unroll
            for (int bn = 0; bn < 4; ++bn)
                b4[bn] = *reinterpret_cast<const float4*>(
                    &Bs[kk8 * 2048 + (wn * 4 + bn) * 128 + lane * 4]);
            #pragma unroll
            for (int am = 0; am < 4; ++am) {
                const float* ab = &As[kk8 * 2048 + (wm * 4 + am) * 256];
                float4 h = *reinterpret_cast<const float4*>(ab + lane * 4);
                float4 l = *reinterpret_cast<const float4*>(ab + 128 + lane * 4);
                uint32_t ah[4] = {__float_as_uint(h.x), __float_as_uint(h.y),
                                  __float_as_uint(h.z), __float_as_uint(h.w)};
                uint32_t al[4] = {__float_as_uint(l.x), __float_as_uint(l.y),
                                  __float_as_uint(l.z), __float_as_uint(l.w)};
                #pragma unroll
                for (int bn = 0; bn < 4; ++bn) {
                    uint32_t bh[2] = {__float_as_uint(b4[bn].x), __float_as_uint(b4[bn].y)};
                    uint32_t bl[2] = {__float_as_uint(b4[bn].z), __float_as_uint(b4[bn].w)};
                    mma_tf32(acc[am][bn], ah, bh);
                    mma_tf32(acc[am][bn], ah, bl);
                    mma_tf32(acc[am][bn], al, bh);
                }
            }
        }
        __syncthreads();
    }

    const int r = lane >> 2;
    const int c2 = (lane & 3) * 2;
    #pragma unroll
    for (int am = 0; am < 4; ++am) {
        #pragma unroll
        for (int bn = 0; bn < 4; ++bn) {
            int col = n0 + wn * 32 + bn * 8 + c2;
            int head = col >> 6, d0 = col & 63;
            int mA = m0 + wm * 64 + am * 16 + r;
            int bb = mA >> 11, ss = mA & (SEQ - 1);
            *reinterpret_cast<float2*>(&out[(((size_t)(bb * NH + head)) * SEQ + ss) * HD + d0]) =
                make_float2(acc[am][bn][0], acc[am][bn][1]);
            int mB = mA + 8;
            int bb2 = mB >> 11, ss2 = mB & (SEQ - 1);
            *reinterpret_cast<float2*>(&out[(((size_t)(bb2 * NH + head)) * SEQ + ss2) * HD + d0]) =
                make_float2(acc[am][bn][2], acc[am][bn][3]);
        }
    }
}

// ----------------------------------------------------------------------------
// Stage 2: flash attention via TF32 mma.  grid = (QTILES, BH), 256 threads.
// Br=128, Bc=64. Warp w owns q-rows [w*16, w*16+16), all 64 keys.
// smem: Qf (unsplit A-frags, 8192) | Kf (hi/lo B-frags, 8192) |
//       Vf (single-tf32 B-frags, 4096) | msk (64 ints) = 82KB.
// P transposed C-frag -> A-frag via warp shuffles (no smem, no barrier).
// ----------------------------------------------------------------------------
constexpr int FL_SMEM = (8192 + 8192 + 4096 + 64) * (int)sizeof(float);  // 82176 B

__global__ void __launch_bounds__(256, 2) flash_kernel(
    const int* __restrict__ attn_mask, const int* __restrict__ mask_future)
{
    extern __shared__ float sm[];
    float* Qf = sm;            // 8192: atom(ma,ka) at (ma*8+ka)*128, unsplit, pre-scaled
    float* Kf = sm + 8192;     // 8192: atom(na,ka) (h0,h1,l0,l1) per lane
    float* Vf = sm + 16384;    // 4096: atom(nd,kk) (h0,h1) per lane (single tf32)
    int* msk = reinterpret_cast<int*>(sm + 20480);

    const int tid = threadIdx.x;
    const int lane = tid & 31;
    const int w = tid >> 5;
    const int gid = lane >> 2, tig = lane & 3;
    const int srcA = (lane & 28) | (tig >> 1);
    const int srcB = srcA + 2;
    const bool odd = (tig & 1) != 0;

    const int qtb = QTILES - 1 - (int)blockIdx.x;   // long blocks first
    const int bh = blockIdx.y;
    const int batch = bh / NH;
    const int q0 = qtb * 128;
    const bool causal = (mask_future[0] != 0);

    const int ig0 = q0 + w * 16 + gid;
    const int ig1 = ig0 + 8;

    // ---- Q fill: warp w -> atoms (w, ka), pre-scaled by 1/8 (exact) ----
    {
        const float* Qg = &g_Q[((size_t)bh * SEQ + q0 + w * 16) * HD];
        #pragma unroll
        for (int ka = 0; ka < 8; ++ka) {
            int col = ka * 8 + tig;
            float a0 = Qg[(size_t)gid * HD + col] * SCALE;
            float a1 = Qg[(size_t)(gid + 8) * HD + col] * SCALE;
            float a2 = Qg[(size_t)gid * HD + col + 4] * SCALE;
            float a3 = Qg[(size_t)(gid + 8) * HD + col + 4] * SCALE;
            *reinterpret_cast<float4*>(&Qf[(w * 8 + ka) * 128 + lane * 4]) =
                make_float4(a0, a1, a2, a3);
        }
    }

    float oacc[8][4] = {};
    float m0 = -1e30f, m1 = -1e30f, l0 = 0.0f, l1 = 0.0f;

    int limit = causal ? (2 * qtb + 2) : NTILES;
    const int limit0 = limit;

    for (int kt = 0; kt < NTILES; ++kt) {
        if (kt >= limit) break;
        const int k0 = kt * 64;
        __syncthreads();   // GEMM1 (Kf,Qf) + GEMM2 (Vf) reads done before refill

        // ---- K fill: warp w -> atoms (na=w, ka), split hi/lo ----
        {
            const float* Kg = &g_K[((size_t)bh * SEQ + k0 + w * 8 + gid) * HD];
            #pragma unroll
            for (int ka = 0; ka < 8; ++ka) {
                int d = ka * 8 + tig;
                float h0, lo0, h1, lo1;
                split_hilo(Kg[d], h0, lo0);
                split_hilo(Kg[d + 4], h1, lo1);
                *reinterpret_cast<float4*>(&Kf[(w * 8 + ka) * 128 + lane * 4]) =
                    make_float4(h0, h1, lo0, lo1);
            }
        }
        // ---- V fill: warp w -> atoms (nd=w, kk), single rna-tf32 ----
        {
            #pragma unroll
            for (int kk = 0; kk < 8; ++kk) {
                const float* Vg = &g_V[((size_t)bh * SEQ + k0 + kk * 8 + tig) * HD + w * 8 + gid];
                float h0 = __uint_as_float(tf32_bits(Vg[0]));
                float h1 = __uint_as_float(tf32_bits(Vg[4 * HD]));
                *reinterpret_cast<float2*>(&Vf[(w * 8 + kk) * 64 + lane * 2]) =
                    make_float2(h0, h1);
            }
        }
        if (tid < 64) msk[tid] = attn_mask[batch * SEQ + k0 + tid];
        __syncthreads();

        // ---- GEMM1: S = (Q*s) K^T, 3xTF32 ----
        float sacc[8][4] = {};
        #pragma unroll
        for (int ka = 0; ka < 8; ++ka) {
            float4 qf = *reinterpret_cast<const float4*>(&Qf[(w * 8 + ka) * 128 + lane * 4]);
            uint32_t ah[4], al[4];
            {
                float h, l;
                split_hilo(qf.x, h, l); ah[0] = __float_as_uint(h); al[0] = __float_as_uint(l);
                split_hilo(qf.y, h, l); ah[1] = __float_as_uint(h); al[1] = __float_as_uint(l);
                split_hilo(qf.z, h, l); ah[2] = __float_as_uint(h); al[2] = __float_as_uint(l);
                split_hilo(qf.w, h, l); ah[3] = __float_as_uint(h); al[3] = __float_as_uint(l);
            }
            #pragma unroll
            for (int na = 0; na < 8; ++na) {
                float4 kf = *reinterpret_cast<const float4*>(&Kf[(na * 8 + ka) * 128 + lane * 4]);
                uint32_t bh2[2] = {__float_as_uint(kf.x), __float_as_uint(kf.y)};
                uint32_t bl2[2] = {__float_as_uint(kf.z), __float_as_uint(kf.w)};
                mma_tf32(sacc[na], ah, bh2);
                mma_tf32(sacc[na], ah, bl2);
                mma_tf32(sacc[na], al, bh2);
            }
        }

        // ---- masks (causal ADD, pad SET) + online softmax ----
        float mx0 = -1e30f, mx1 = -1e30f;
        #pragma unroll
        for (int na = 0; na < 8; ++na) {
            int j0 = na * 8 + 2 * tig, j1 = j0 + 1;
            int jg0 = k0 + j0, jg1 = k0 + j1;
            float s0 = sacc[na][0], s1 = sacc[na][1];
            float s2 = sacc[na][2], s3 = sacc[na][3];
            if (causal) {
                if (jg0 > ig0) s0 += NEGV;
                if (jg1 > ig0) s1 += NEGV;
                if (jg0 > ig1) s2 += NEGV;
                if (jg1 > ig1) s3 += NEGV;
            }
            if (msk[j0] == 0) { s0 = NEGV; s2 = NEGV; }
            if (msk[j1] == 0) { s1 = NEGV; s3 = NEGV; }
            sacc[na][0] = s0; sacc[na][1] = s1;
            sacc[na][2] = s2; sacc[na][3] = s3;
            mx0 = fmaxf(mx0, fmaxf(s0, s1));
            mx1 = fmaxf(mx1, fmaxf(s2, s3));
        }
        mx0 = fmaxf(mx0, __shfl_xor_sync(0xffffffffu, mx0, 1));
        mx0 = fmaxf(mx0, __shfl_xor_sync(0xffffffffu, mx0, 2));
        mx1 = fmaxf(mx1, __shfl_xor_sync(0xffffffffu, mx1, 1));
        mx1 = fmaxf(mx1, __shfl_xor_sync(0xffffffffu, mx1, 2));

        float mn0 = fmaxf(m0, mx0), mn1 = fmaxf(m1, mx1);
        float alpha0 = __expf(m0 - mn0), alpha1 = __expf(m1 - mn1);
        float sum0 = 0.0f, sum1 = 0.0f;
        #pragma unroll
        for (int na = 0; na < 8; ++na) {
            float p0 = __expf(sacc[na][0] - mn0);
            float p1 = __expf(sacc[na][1] - mn0);
            float p2 = __expf(sacc[na][2] - mn1);
            float p3 = __expf(sacc[na][3] - mn1);
            sacc[na][0] = p0; sacc[na][1] = p1;
            sacc[na][2] = p2; sacc[na][3] = p3;
            sum0 += p0 + p1;
            sum1 += p2 + p3;
        }
        sum0 += __shfl_xor_sync(0xffffffffu, sum0, 1);
        sum0 += __shfl_xor_sync(0xffffffffu, sum0, 2);
        sum1 += __shfl_xor_sync(0xffffffffu, sum1, 1);
        sum1 += __shfl_xor_sync(0xffffffffu, sum1, 2);
        l0 = l0 * alpha0 + sum0;
        l1 = l1 * alpha1 + sum1;
        m0 = mn0; m1 = mn1;
        #pragma unroll
        for (int na = 0; na < 8; ++na) {
            oacc[na][0] *= alpha0; oacc[na][1] *= alpha0;
            oacc[na][2] *= alpha1; oacc[na][3] *= alpha1;
        }

        // ---- GEMM2: O += P V; P C-frag -> A-frag via shuffles, V single tf32 ----
        #pragma unroll
        for (int pka = 0; pka < 8; ++pka) {
            float pr0 = __uint_as_float(tf32_bits(sacc[pka][0]));
            float pr1 = __uint_as_float(tf32_bits(sacc[pka][1]));
            float pr2 = __uint_as_float(tf32_bits(sacc[pka][2]));
            float pr3 = __uint_as_float(tf32_bits(sacc[pka][3]));
            float v0A = __shfl_sync(0xffffffffu, pr0, srcA);
            float v1A = __shfl_sync(0xffffffffu, pr1, srcA);
            float v2A = __shfl_sync(0xffffffffu, pr2, srcA);
            float v3A = __shfl_sync(0xffffffffu, pr3, srcA);
            float v0B = __shfl_sync(0xffffffffu, pr0, srcB);
            float v1B = __shfl_sync(0xffffffffu, pr1, srcB);
            float v2B = __shfl_sync(0xffffffffu, pr2, srcB);
            float v3B = __shfl_sync(0xffffffffu, pr3, srcB);
            uint32_t pa[4];
            pa[0] = __float_as_uint(odd ? v1A : v0A);
            pa[1] = __float_as_uint(odd ? v3A : v2A);
            pa[2] = __float_as_uint(odd ? v1B : v0B);
            pa[3] = __float_as_uint(odd ? v3B : v2B);
            #pragma unroll
            for (int nd = 0; nd < 8; ++nd) {
                float2 vf = *reinterpret_cast<const float2*>(&Vf[(nd * 8 + pka) * 64 + lane * 2]);
                uint32_t vh[2] = {__float_as_uint(vf.x), __float_as_uint(vf.y)};
                mma_tf32(oacc[nd], pa, vh);
            }
        }

        // ---- all-padded rows attend to future keys (reference semantics) ----
        if (causal && kt == limit0 - 1 && limit0 != NTILES) {
            int lack = (m0 <= -5000.0f || m1 <= -5000.0f) ? 1 : 0;
            if (__syncthreads_or(lack)) limit = NTILES;
        }
    }

    // ---- epilogue: normalize, store head-major ----
    float il0 = 1.0f / l0, il1 = 1.0f / l1;
    #pragma unroll
    for (int nd = 0; nd < 8; ++nd) {
        int col = nd * 8 + 2 * tig;
        *reinterpret_cast<float2*>(&g_O[((size_t)bh * SEQ + ig0) * HD + col]) =
            make_float2(oacc[nd][0] * il0, oacc[nd][1] * il0);
        *reinterpret_cast<float2*>(&g_O[((size_t)bh * SEQ + ig1) * HD + col]) =
            make_float2(oacc[nd][2] * il1, oacc[nd][3] * il1);
    }
}

// ----------------------------------------------------------------------------
// Stage 3: output projection (R8-validated SIMT, unchanged).
// ----------------------------------------------------------------------------
__global__ void __launch_bounds__(256) out_proj_kernel(
    const float* __restrict__ Wo, float* __restrict__ out)
{
    __shared__ float As[16 * 128];
    __shared__ float Bs[16 * 64];

    const int n0 = blockIdx.x * 64;
    const int m0 = blockIdx.y * 128;
    const int tid = threadIdx.x;
    const int tx = tid & 15, ty = tid >> 4;

    const int am = tid >> 1;
    const int ak = (tid & 1) * 8;
    const int brow = tid >> 4;
    const int bcol = (tid & 15) * 4;

    const int m = m0 + am;
    const int bb = m >> 11;
    const int ss = m & (SEQ - 1);

    float acc[8][4] = {};

    for (int k0 = 0; k0 < DM; k0 += 16) {
        int kidx = k0 + ak;
        int h = kidx >> 6, dd = kidx & 63;
        const float* src = &g_O[(((size_t)(bb * NH + h)) * SEQ + ss) * HD + dd];
        float4 a0 = *reinterpret_cast<const float4*>(src);
        float4 a1 = *reinterpret_cast<const float4*>(src + 4);
        As[(ak + 0) * 128 + am] = a0.x;
        As[(ak + 1) * 128 + am] = a0.y;
        As[(ak + 2) * 128 + am] = a0.z;
        As[(ak + 3) * 128 + am] = a0.w;
        As[(ak + 4) * 128 + am] = a1.x;
        As[(ak + 5) * 128 + am] = a1.y;
        As[(ak + 6) * 128 + am] = a1.z;
        As[(ak + 7) * 128 + am] = a1.w;
        *reinterpret_cast<float4*>(&Bs[brow * 64 + bcol]) =
            *reinterpret_cast<const float4*>(&Wo[(size_t)(k0 + brow) * DM + n0 + bcol]);
        __syncthreads();

        #pragma unroll
        for (int kk = 0; kk < 16; ++kk) {
            float4 ra0 = *reinterpret_cast<float4*>(&As[kk * 128 + ty * 8]);
            float4 ra1 = *reinterpret_cast<float4*>(&As[kk * 128 + ty * 8 + 4]);
            float4 b   = *reinterpret_cast<float4*>(&Bs[kk * 64 + tx * 4]);
            float ar[8] = {ra0.x, ra0.y, ra0.z, ra0.w, ra1.x, ra1.y, ra1.z, ra1.w};
            #pragma unroll
            for (int i = 0; i < 8; ++i) {
                acc[i][0] += ar[i] * b.x;
                acc[i][1] += ar[i] * b.y;
                acc[i][2] += ar[i] * b.z;
                acc[i][3] += ar[i] * b.w;
            }
        }
        __syncthreads();
    }

    #pragma unroll
    for (int i = 0; i < 8; ++i) {
        int mm = m0 + ty * 8 + i;
        *reinterpret_cast<float4*>(&out[(size_t)mm * DM + n0 + tx * 4]) =
            make_float4(acc[i][0], acc[i][1], acc[i][2], acc[i][3]);
    }
}

// ----------------------------------------------------------------------------
extern "C" void kernel_launch(void* const* d_in, const int* in_sizes, int n_in,
                              void* d_out, int out_size)
{
    const float* q    = (const float*)d_in[0];
    const float* k    = (const float*)d_in[1];
    const float* v    = (const float*)d_in[2];
    const int*   mask = (const int*)d_in[3];
    const float* Wq   = (const float*)d_in[4];
    const float* Wk   = (const float*)d_in[5];
    const float* Wv   = (const float*)d_in[6];
    const float* Wo   = (const float*)d_in[7];
    const int*   mfut = (const int*)d_in[8];
    float* out = (float*)d_out;

    static bool attr_set = false;
    if (!attr_set) {
        cudaFuncSetAttribute(qkv_mma_kernel, cudaFuncAttributeMaxDynamicSharedMemorySize, QKV_SMEM);
        cudaFuncSetAttribute(flash_kernel, cudaFuncAttributeMaxDynamicSharedMemorySize, FL_SMEM);
        attr_set = true;
    }

    pre_x_kernel<<<dim3(KATOMS * MATOMS / 8, 3), 256>>>(q, k, v);
    pre_w_kernel<<<dim3(KATOMS * NATOMS / 8, 3), 256>>>(Wq, Wk, Wv);
    qkv_mma_kernel<<<dim3(DM / 128, MTOT / 128, 3), 256, QKV_SMEM>>>();
    flash_kernel<<<dim3(QTILES, BH), 256, FL_SMEM>>>(mask, mfut);
    out_proj_kernel<<<dim3(DM / 64, MTOT / 128), 256>>>(Wo, out);
}

// round 16
// speedup vs baseline: 1.7584x; 1.0796x over previous
#include <cuda_runtime.h>
#include <cstdint>

// ----------------------------------------------------------------------------
// MultiHeadAttention, fp32 semantics.
// Stage 0: preconvert X,W -> tf32 hi/lo fragment-major (R12-validated).
// Stage 1: QKV projections via 3xTF32 mma.sync (R12-validated).
// Stage 2: flash attention, plain-TF32 QK^T + single-TF32 PV, double-buffered
//          K/V with register prefetch, one barrier per KV tile (NEW).
// Stage 3: output projection SIMT SGEMM (R8-validated).
// ----------------------------------------------------------------------------

constexpr int BATCH = 2;
constexpr int SEQ   = 2048;
constexpr int DM    = 768;
constexpr int NH    = 12;
constexpr int HD    = 64;
constexpr int BH    = BATCH * NH;   // 24
constexpr int MTOT  = BATCH * SEQ;  // 4096
constexpr int NTILES = SEQ / 64;    // 32
constexpr int QTILES = SEQ / 128;   // 16
constexpr float NEGV  = -10000.0f;
constexpr float SCALE = 0.125f;

constexpr int KATOMS = DM / 8;      // 96
constexpr int MATOMS = MTOT / 16;   // 256
constexpr int NATOMS = DM / 8;      // 96

__device__ float g_Q[BATCH * NH * SEQ * HD];
__device__ float g_K[BATCH * NH * SEQ * HD];
__device__ float g_V[BATCH * NH * SEQ * HD];
__device__ float g_O[BATCH * NH * SEQ * HD];

__device__ __align__(16) float g_Xs[3][KATOMS * MATOMS * 256];
__device__ __align__(16) float g_Ws[3][KATOMS * NATOMS * 128];

__device__ __forceinline__ uint32_t tf32_bits(float x) {
    uint32_t u;
    asm("cvt.rna.tf32.f32 %0, %1;" : "=r"(u) : "f"(x));
    return u;
}
__device__ __forceinline__ float tf32f(float x) {
    return __uint_as_float(tf32_bits(x));
}
__device__ __forceinline__ void split_hilo(float x, float& h, float& l) {
    uint32_t hb = tf32_bits(x);
    h = __uint_as_float(hb);
    l = __uint_as_float(tf32_bits(x - h));
}
__device__ __forceinline__ void mma_tf32(float d[4], const uint32_t a[4], const uint32_t b[2]) {
    asm volatile(
        "mma.sync.aligned.m16n8k8.row.col.f32.tf32.tf32.f32 "
        "{%0,%1,%2,%3}, {%4,%5,%6,%7}, {%8,%9}, {%0,%1,%2,%3};"
        : "+f"(d[0]), "+f"(d[1]), "+f"(d[2]), "+f"(d[3])
        : "r"(a[0]), "r"(a[1]), "r"(a[2]), "r"(a[3]), "r"(b[0]), "r"(b[1]));
}

// ----------------------------------------------------------------------------
// Stage 0a/0b: preconvert (R12-validated, unchanged).
// ----------------------------------------------------------------------------
__global__ void __launch_bounds__(256) pre_x_kernel(
    const float* __restrict__ q, const float* __restrict__ k, const float* __restrict__ v)
{
    const int z = blockIdx.y;
    const float* X = (z == 0) ? q : (z == 1) ? k : v;
    float* dst = g_Xs[z];

    const int wid = threadIdx.x >> 5, lane = threadIdx.x & 31;
    const int atom = blockIdx.x * 8 + wid;
    const int katom = atom >> 8;
    const int matom = atom & 255;
    const int gid = lane >> 2, tig = lane & 3;
    const int m = matom * 16, kk = katom * 8;

    float a0 = X[(size_t)(m + gid) * DM + kk + tig];
    float a1 = X[(size_t)(m + gid + 8) * DM + kk + tig];
    float a2 = X[(size_t)(m + gid) * DM + kk + tig + 4];
    float a3 = X[(size_t)(m + gid + 8) * DM + kk + tig + 4];

    float h0, l0, h1, l1, h2, l2, h3, l3;
    split_hilo(a0, h0, l0); split_hilo(a1, h1, l1);
    split_hilo(a2, h2, l2); split_hilo(a3, h3, l3);

    float* base = dst + (size_t)atom * 256;
    *reinterpret_cast<float4*>(base + lane * 4)       = make_float4(h0, h1, h2, h3);
    *reinterpret_cast<float4*>(base + 128 + lane * 4) = make_float4(l0, l1, l2, l3);
}

__global__ void __launch_bounds__(256) pre_w_kernel(
    const float* __restrict__ Wq, const float* __restrict__ Wk, const float* __restrict__ Wv)
{
    const int z = blockIdx.y;
    const float* W = (z == 0) ? Wq : (z == 1) ? Wk : Wv;
    float* dst = g_Ws[z];

    const int wid = threadIdx.x >> 5, lane = threadIdx.x & 31;
    const int atom = blockIdx.x * 8 + wid;
    const int katom = atom / NATOMS;
    const int natom = atom - katom * NATOMS;
    const int gid = lane >> 2, tig = lane & 3;

    float b0 = W[(size_t)(katom * 8 + tig) * DM + natom * 8 + gid];
    float b1 = W[(size_t)(katom * 8 + tig + 4) * DM + natom * 8 + gid];

    float h0, l0, h1, l1;
    split_hilo(b0, h0, l0); split_hilo(b1, h1, l1);

    *reinterpret_cast<float4*>(dst + (size_t)atom * 128 + lane * 4) =
        make_float4(h0, h1, l0, l1);
}

// ----------------------------------------------------------------------------
// Stage 1: QKV projections via 3xTF32 mma (R12-validated, unchanged).
// ----------------------------------------------------------------------------
constexpr int QKV_SMEM = 16384 * (int)sizeof(float);   // 64KB

__global__ void __launch_bounds__(256, 2) qkv_mma_kernel()
{
    extern __shared__ float smm[];
    float* As = smm;
    float* Bs = smm + 8192;

    const int z = blockIdx.z;
    const float* Af = g_Xs[z];
    const float* Bf = g_Ws[z];
    float* out = (z == 0) ? g_Q : (z == 1) ? g_K : g_V;

    const int n0 = blockIdx.x * 128;
    const int m0 = blockIdx.y * 128;
    const int tid = threadIdx.x;
    const int lane = tid & 31;
    const int wid = tid >> 5;
    const int wm = wid >> 2, wn = wid & 3;

    float acc[4][4][4] = {};

    for (int ch = 0; ch < DM / 32; ++ch) {
        #pragma unroll
        for (int kl = 0; kl < 4; ++kl) {
            const int kg = ch * 4 + kl;
            const float4* asrc = reinterpret_cast<const float4*>(
                Af + ((size_t)kg * MATOMS + (m0 >> 4)) * 256);
            float4* adst = reinterpret_cast<float4*>(As + kl * 2048);
            adst[tid * 2]     = asrc[tid * 2];
            adst[tid * 2 + 1] = asrc[tid * 2 + 1];
            const float4* bsrc = reinterpret_cast<const float4*>(
                Bf + ((size_t)kg * NATOMS + (n0 >> 3)) * 128);
            float4* bdst = reinterpret_cast<float4*>(Bs + kl * 2048);
            bdst[tid * 2]     = bsrc[tid * 2];
            bdst[tid * 2 + 1] = bsrc[tid * 2 + 1];
        }
        __syncthreads();

        #pragma unroll
        for (int kk8 = 0; kk8 < 4; ++kk8) {
            float4 b4[4];
            #pragma unroll
            for (int bn = 0; bn < 4; ++bn)
                b4[bn] = *reinterpret_cast<const float4*>(
                    &Bs[kk8 * 2048 + (wn * 4 + bn) * 128 + lane * 4]);
            #pragma unroll
            for (int am = 0; am < 4; ++am) {
                const float* ab = &As[kk8 * 2048 + (wm * 4 + am) * 256];
                float4 h = *reinterpret_cast<const float4*>(ab + lane * 4);
                float4 l = *reinterpret_cast<const float4*>(ab + 128 + lane * 4);
                uint32_t ah[4] = {__float_as_uint(h.x), __float_as_uint(h.y),
                                  __float_as_uint(h.z), __float_as_uint(h.w)};
                uint32_t al[4] = {__float_as_uint(l.x), __float_as_uint(l.y),
                                  __float_as_uint(l.z), __float_as_uint(l.w)};
                #pragma unroll
                for (int bn = 0; bn < 4; ++bn) {
                    uint32_t bh[2] = {__float_as_uint(b4[bn].x), __float_as_uint(b4[bn].y)};
                    uint32_t bl[2] = {__float_as_uint(b4[bn].z), __float_as_uint(b4[bn].w)};
                    mma_tf32(acc[am][bn], ah, bh);
                    mma_tf32(acc[am][bn], ah, bl);
                    mma_tf32(acc[am][bn], al, bh);
                }
            }
        }
        __syncthreads();
    }

    const int r = lane >> 2;
    const int c2 = (lane & 3) * 2;
    #pragma unroll
    for (int am = 0; am < 4; ++am) {
        #pragma unroll
        for (int bn = 0; bn < 4; ++bn) {
            int col = n0 + wn * 32 + bn * 8 + c2;
            int head = col >> 6, d0 = col & 63;
            int mA = m0 + wm * 64 + am * 16 + r;
            int bb = mA >> 11, ss = mA & (SEQ - 1);
            *reinterpret_cast<float2*>(&out[(((size_t)(bb * NH + head)) * SEQ + ss) * HD + d0]) =
                make_float2(acc[am][bn][0], acc[am][bn][1]);
            int mB = mA + 8;
            int bb2 = mB >> 11, ss2 = mB & (SEQ - 1);
            *reinterpret_cast<float2*>(&out[(((size_t)(bb2 * NH + head)) * SEQ + ss2) * HD + d0]) =
                make_float2(acc[am][bn][2], acc[am][bn][3]);
        }
    }
}

// ----------------------------------------------------------------------------
// Stage 2: flash attention, plain-TF32 QK^T, single-TF32 PV, double-buffered
// K/V with register prefetch. grid = (QTILES, BH), 256 threads.
// Br=128, Bc=64. Warp w owns q-rows [w*16, w*16+16), all 64 keys.
// smem: Qf (tf32 A-frags, 8192) | Kf[2] (tf32 B-frags, 2x4096) |
//       Vf[2] (tf32 B-frags, 2x4096) | msk[2][64].
// ----------------------------------------------------------------------------
constexpr int FL_SMEM = (8192 + 8192 + 8192 + 128) * (int)sizeof(float);  // 98816 B

__global__ void __launch_bounds__(256, 2) flash_kernel(
    const int* __restrict__ attn_mask, const int* __restrict__ mask_future)
{
    extern __shared__ float sm[];
    float* Qf = sm;                        // 8192: atom(ma,ka), 4 tf32/lane
    float* Kbuf[2] = {sm + 8192, sm + 12288};   // 4096 each: atom(na,ka), 2 tf32/lane
    float* Vbuf[2] = {sm + 16384, sm + 20480};  // 4096 each: atom(nd,kk), 2 tf32/lane
    int* mbuf[2] = {reinterpret_cast<int*>(sm + 24576),
                    reinterpret_cast<int*>(sm + 24576) + 64};

    const int tid = threadIdx.x;
    const int lane = tid & 31;
    const int w = tid >> 5;
    const int gid = lane >> 2, tig = lane & 3;
    const int srcA = (lane & 28) | (tig >> 1);
    const int srcB = srcA + 2;
    const bool odd = (tig & 1) != 0;

    const int qtb = QTILES - 1 - (int)blockIdx.x;   // long blocks first
    const int bh = blockIdx.y;
    const int batch = bh / NH;
    const int q0 = qtb * 128;
    const bool causal = (mask_future[0] != 0);

    const int ig0 = q0 + w * 16 + gid;
    const int ig1 = ig0 + 8;

    // ---- Q fill: warp w -> atoms (w, ka), pre-scaled by 1/8, rna-tf32 ----
    {
        const float* Qg = &g_Q[((size_t)bh * SEQ + q0 + w * 16) * HD];
        #pragma unroll
        for (int ka = 0; ka < 8; ++ka) {
            int col = ka * 8 + tig;
            float a0 = tf32f(Qg[(size_t)gid * HD + col] * SCALE);
            float a1 = tf32f(Qg[(size_t)(gid + 8) * HD + col] * SCALE);
            float a2 = tf32f(Qg[(size_t)gid * HD + col + 4] * SCALE);
            float a3 = tf32f(Qg[(size_t)(gid + 8) * HD + col + 4] * SCALE);
            *reinterpret_cast<float4*>(&Qf[(w * 8 + ka) * 128 + lane * 4]) =
                make_float4(a0, a1, a2, a3);
        }
    }

    float oacc[8][4] = {};
    float m0 = -1e30f, m1 = -1e30f, l0 = 0.0f, l1 = 0.0f;

    int limit = causal ? (2 * qtb + 2) : NTILES;
    const int limit0 = limit;

    // ---- prologue: fill tile 0 into buffer 0 ----
    {
        const float* Kg = &g_K[((size_t)bh * SEQ + w * 8 + gid) * HD];
        #pragma unroll
        for (int ka = 0; ka < 8; ++ka) {
            float h0 = tf32f(Kg[ka * 8 + tig]);
            float h1 = tf32f(Kg[ka * 8 + tig + 4]);
            *reinterpret_cast<float2*>(&Kbuf[0][(w * 8 + ka) * 64 + lane * 2]) =
                make_float2(h0, h1);
        }
        #pragma unroll
        for (int kk = 0; kk < 8; ++kk) {
            const float* Vg = &g_V[((size_t)bh * SEQ + kk * 8 + tig) * HD + w * 8 + gid];
            *reinterpret_cast<float2*>(&Vbuf[0][(w * 8 + kk) * 64 + lane * 2]) =
                make_float2(tf32f(Vg[0]), tf32f(Vg[4 * HD]));
        }
        if (tid < 64) mbuf[0][tid] = attn_mask[batch * SEQ + tid];
    }
    __syncthreads();

    for (int kt = 0; kt < NTILES; ++kt) {
        if (kt >= limit) break;
        const int buf = kt & 1;
        const int k0 = kt * 64;
        const bool pre = (kt + 1 < NTILES);

        // ---- prefetch tile kt+1 into registers (latency hidden under MMA) ----
        float kr[16], vr[16];
        int mr = 0;
        if (pre) {
            const int k0n = k0 + 64;
            const float* Kg = &g_K[((size_t)bh * SEQ + k0n + w * 8 + gid) * HD];
            #pragma unroll
            for (int ka = 0; ka < 8; ++ka) {
                kr[ka * 2]     = Kg[ka * 8 + tig];
                kr[ka * 2 + 1] = Kg[ka * 8 + tig + 4];
            }
            #pragma unroll
            for (int kk = 0; kk < 8; ++kk) {
                const float* Vg = &g_V[((size_t)bh * SEQ + k0n + kk * 8 + tig) * HD + w * 8 + gid];
                vr[kk * 2]     = Vg[0];
                vr[kk * 2 + 1] = Vg[4 * HD];
            }
            if (tid < 64) mr = attn_mask[batch * SEQ + k0n + tid];
        }

        // ---- GEMM1: S = (Q*s) K^T, plain TF32 ----
        const float* Kf = Kbuf[buf];
        const float* Vf = Vbuf[buf];
        const int* msk = mbuf[buf];

        float sacc[8][4] = {};
        #pragma unroll
        for (int ka = 0; ka < 8; ++ka) {
            float4 qf = *reinterpret_cast<const float4*>(&Qf[(w * 8 + ka) * 128 + lane * 4]);
            uint32_t qa[4] = {__float_as_uint(qf.x), __float_as_uint(qf.y),
                              __float_as_uint(qf.z), __float_as_uint(qf.w)};
            #pragma unroll
            for (int na = 0; na < 8; ++na) {
                float2 kf = *reinterpret_cast<const float2*>(&Kf[(na * 8 + ka) * 64 + lane * 2]);
                uint32_t kb[2] = {__float_as_uint(kf.x), __float_as_uint(kf.y)};
                mma_tf32(sacc[na], qa, kb);
            }
        }

        // ---- masks (causal ADD, pad SET) + online softmax ----
        float mx0 = -1e30f, mx1 = -1e30f;
        #pragma unroll
        for (int na = 0; na < 8; ++na) {
            int j0 = na * 8 + 2 * tig, j1 = j0 + 1;
            int jg0 = k0 + j0, jg1 = k0 + j1;
            float s0 = sacc[na][0], s1 = sacc[na][1];
            float s2 = sacc[na][2], s3 = sacc[na][3];
            if (causal) {
                if (jg0 > ig0) s0 += NEGV;
                if (jg1 > ig0) s1 += NEGV;
                if (jg0 > ig1) s2 += NEGV;
                if (jg1 > ig1) s3 += NEGV;
            }
            if (msk[j0] == 0) { s0 = NEGV; s2 = NEGV; }
            if (msk[j1] == 0) { s1 = NEGV; s3 = NEGV; }
            sacc[na][0] = s0; sacc[na][1] = s1;
            sacc[na][2] = s2; sacc[na][3] = s3;
            mx0 = fmaxf(mx0, fmaxf(s0, s1));
            mx1 = fmaxf(mx1, fmaxf(s2, s3));
        }
        mx0 = fmaxf(mx0, __shfl_xor_sync(0xffffffffu, mx0, 1));
        mx0 = fmaxf(mx0, __shfl_xor_sync(0xffffffffu, mx0, 2));
        mx1 = fmaxf(mx1, __shfl_xor_sync(0xffffffffu, mx1, 1));
        mx1 = fmaxf(mx1, __shfl_xor_sync(0xffffffffu, mx1, 2));

        float mn0 = fmaxf(m0, mx0), mn1 = fmaxf(m1, mx1);
        float alpha0 = __expf(m0 - mn0), alpha1 = __expf(m1 - mn1);
        float sum0 = 0.0f, sum1 = 0.0f;
        #pragma unroll
        for (int na = 0; na < 8; ++na) {
            float p0 = __expf(sacc[na][0] - mn0);
            float p1 = __expf(sacc[na][1] - mn0);
            float p2 = __expf(sacc[na][2] - mn1);
            float p3 = __expf(sacc[na][3] - mn1);
            sacc[na][0] = p0; sacc[na][1] = p1;
            sacc[na][2] = p2; sacc[na][3] = p3;
            sum0 += p0 + p1;
            sum1 += p2 + p3;
        }
        sum0 += __shfl_xor_sync(0xffffffffu, sum0, 1);
        sum0 += __shfl_xor_sync(0xffffffffu, sum0, 2);
        sum1 += __shfl_xor_sync(0xffffffffu, sum1, 1);
        sum1 += __shfl_xor_sync(0xffffffffu, sum1, 2);
        l0 = l0 * alpha0 + sum0;
        l1 = l1 * alpha1 + sum1;
        m0 = mn0; m1 = mn1;
        #pragma unroll
        for (int na = 0; na < 8; ++na) {
            oacc[na][0] *= alpha0; oacc[na][1] *= alpha0;
            oacc[na][2] *= alpha1; oacc[na][3] *= alpha1;
        }

        // ---- GEMM2: O += P V; P C-frag -> A-frag via shuffles, V single tf32 ----
        #pragma unroll
        for (int pka = 0; pka < 8; ++pka) {
            float pr0 = __uint_as_float(tf32_bits(sacc[pka][0]));
            float pr1 = __uint_as_float(tf32_bits(sacc[pka][1]));
            float pr2 = __uint_as_float(tf32_bits(sacc[pka][2]));
            float pr3 = __uint_as_float(tf32_bits(sacc[pka][3]));
            float v0A = __shfl_sync(0xffffffffu, pr0, srcA);
            float v1A = __shfl_sync(0xffffffffu, pr1, srcA);
            float v2A = __shfl_sync(0xffffffffu, pr2, srcA);
            float v3A = __shfl_sync(0xffffffffu, pr3, srcA);
            float v0B = __shfl_sync(0xffffffffu, pr0, srcB);
            float v1B = __shfl_sync(0xffffffffu, pr1, srcB);
            float v2B = __shfl_sync(0xffffffffu, pr2, srcB);
            float v3B = __shfl_sync(0xffffffffu, pr3, srcB);
            uint32_t pa[4];
            pa[0] = __float_as_uint(odd ? v1A : v0A);
            pa[1] = __float_as_uint(odd ? v3A : v2A);
            pa[2] = __float_as_uint(odd ? v1B : v0B);
            pa[3] = __float_as_uint(odd ? v3B : v2B);
            #pragma unroll
            for (int nd = 0; nd < 8; ++nd) {
                float2 vf = *reinterpret_cast<const float2*>(&Vf[(nd * 8 + pka) * 64 + lane * 2]);
                uint32_t vh[2] = {__float_as_uint(vf.x), __float_as_uint(vf.y)};
                mma_tf32(oacc[nd], pa, vh);
            }
        }

        // ---- store prefetched tile kt+1 into the other buffer ----
        if (pre) {
            float* Kn = Kbuf[buf ^ 1];
            float* Vn = Vbuf[buf ^ 1];
            #pragma unroll
            for (int ka = 0; ka < 8; ++ka)
                *reinterpret_cast<float2*>(&Kn[(w * 8 + ka) * 64 + lane * 2]) =
                    make_float2(tf32f(kr[ka * 2]), tf32f(kr[ka * 2 + 1]));
            #pragma unroll
            for (int kk = 0; kk < 8; ++kk)
                *reinterpret_cast<float2*>(&Vn[(w * 8 + kk) * 64 + lane * 2]) =
                    make_float2(tf32f(vr[kk * 2]), tf32f(vr[kk * 2 + 1]));
            if (tid < 64) mbuf[buf ^ 1][tid] = mr;
        }

        // ---- all-padded rows attend to future keys (reference semantics) ----
        if (causal && kt == limit0 - 1 && limit0 != NTILES) {
            int lack = (m0 <= -5000.0f || m1 <= -5000.0f) ? 1 : 0;
            if (__syncthreads_or(lack)) limit = NTILES;
        }
        __syncthreads();
    }

    // ---- epilogue: normalize, store head-major ----
    float il0 = 1.0f / l0, il1 = 1.0f / l1;
    #pragma unroll
    for (int nd = 0; nd < 8; ++nd) {
        int col = nd * 8 + 2 * tig;
        *reinterpret_cast<float2*>(&g_O[((size_t)bh * SEQ + ig0) * HD + col]) =
            make_float2(oacc[nd][0] * il0, oacc[nd][1] * il0);
        *reinterpret_cast<float2*>(&g_O[((size_t)bh * SEQ + ig1) * HD + col]) =
            make_float2(oacc[nd][2] * il1, oacc[nd][3] * il1);
    }
}

// ----------------------------------------------------------------------------
// Stage 3: output projection (R8-validated SIMT, unchanged).
// ----------------------------------------------------------------------------
__global__ void __launch_bounds__(256) out_proj_kernel(
    const float* __restrict__ Wo, float* __restrict__ out)
{
    __shared__ float As[16 * 128];
    __shared__ float Bs[16 * 64];

    const int n0 = blockIdx.x * 64;
    const int m0 = blockIdx.y * 128;
    const int tid = threadIdx.x;
    const int tx = tid & 15, ty = tid >> 4;

    const int am = tid >> 1;
    const int ak = (tid & 1) * 8;
    const int brow = tid >> 4;
    const int bcol = (tid & 15) * 4;

    const int m = m0 + am;
    const int bb = m >> 11;
    const int ss = m & (SEQ - 1);

    float acc[8][4] = {};

    for (int k0 = 0; k0 < DM; k0 += 16) {
        int kidx = k0 + ak;
        int h = kidx >> 6, dd = kidx & 63;
        const float* src = &g_O[(((size_t)(bb * NH + h)) * SEQ + ss) * HD + dd];
        float4 a0 = *reinterpret_cast<const float4*>(src);
        float4 a1 = *reinterpret_cast<const float4*>(src + 4);
        As[(ak + 0) * 128 + am] = a0.x;
        As[(ak + 1) * 128 + am] = a0.y;
        As[(ak + 2) * 128 + am] = a0.z;
        As[(ak + 3) * 128 + am] = a0.w;
        As[(ak + 4) * 128 + am] = a1.x;
        As[(ak + 5) * 128 + am] = a1.y;
        As[(ak + 6) * 128 + am] = a1.z;
        As[(ak + 7) * 128 + am] = a1.w;
        *reinterpret_cast<float4*>(&Bs[brow * 64 + bcol]) =
            *reinterpret_cast<const float4*>(&Wo[(size_t)(k0 + brow) * DM + n0 + bcol]);
        __syncthreads();

        #pragma unroll
        for (int kk = 0; kk < 16; ++kk) {
            float4 ra0 = *reinterpret_cast<float4*>(&As[kk * 128 + ty * 8]);
            float4 ra1 = *reinterpret_cast<float4*>(&As[kk * 128 + ty * 8 + 4]);
            float4 b   = *reinterpret_cast<float4*>(&Bs[kk * 64 + tx * 4]);
            float ar[8] = {ra0.x, ra0.y, ra0.z, ra0.w, ra1.x, ra1.y, ra1.z, ra1.w};
            #pragma unroll
            for (int i = 0; i < 8; ++i) {
                acc[i][0] += ar[i] * b.x;
                acc[i][1] += ar[i] * b.y;
                acc[i][2] += ar[i] * b.z;
                acc[i][3] += ar[i] * b.w;
            }
        }
        __syncthreads();
    }

    #pragma unroll
    for (int i = 0; i < 8; ++i) {
        int mm = m0 + ty * 8 + i;
        *reinterpret_cast<float4*>(&out[(size_t)mm * DM + n0 + tx * 4]) =
            make_float4(acc[i][0], acc[i][1], acc[i][2], acc[i][3]);
    }
}

// ----------------------------------------------------------------------------
extern "C" void kernel_launch(void* const* d_in, const int* in_sizes, int n_in,
                              void* d_out, int out_size)
{
    const float* q    = (const float*)d_in[0];
    const float* k    = (const float*)d_in[1];
    const float* v    = (const float*)d_in[2];
    const int*   mask = (const int*)d_in[3];
    const float* Wq   = (const float*)d_in[4];
    const float* Wk   = (const float*)d_in[5];
    const float* Wv   = (const float*)d_in[6];
    const float* Wo   = (const float*)d_in[7];
    const int*   mfut = (const int*)d_in[8];
    float* out = (float*)d_out;

    static bool attr_set = false;
    if (!attr_set) {
        cudaFuncSetAttribute(qkv_mma_kernel, cudaFuncAttributeMaxDynamicSharedMemorySize, QKV_SMEM);
        cudaFuncSetAttribute(flash_kernel, cudaFuncAttributeMaxDynamicSharedMemorySize, FL_SMEM);
        attr_set = true;
    }

    pre_x_kernel<<<dim3(KATOMS * MATOMS / 8, 3), 256>>>(q, k, v);
    pre_w_kernel<<<dim3(KATOMS * NATOMS / 8, 3), 256>>>(Wq, Wk, Wv);
    qkv_mma_kernel<<<dim3(DM / 128, MTOT / 128, 3), 256, QKV_SMEM>>>();
    flash_kernel<<<dim3(QTILES, BH), 256, FL_SMEM>>>(mask, mfut);
    out_proj_kernel<<<dim3(DM / 64, MTOT / 128), 256>>>(Wo, out);
}